// round 1
// baseline (speedup 1.0000x reference)
#include <cuda_runtime.h>
#include <math.h>

#define B 8
#define S 1024
#define D 512
#define H 8
#define HD 64
#define BS (B*S)
#define SCALE 0.044194173824159216f  // 1/sqrt(512)

// ---------------- scratch (static device globals; no allocation) ----------------
__device__ float g_h[BS * D];          // 16 MB  h = emb[x] + pos
__device__ float g_w[BS];              // width (raw -> normalized)
__device__ float g_q[B * H * S * HD];  // 16 MB, layout [b,h,s,d]
__device__ float g_k[B * H * S * HD];
__device__ float g_v[B * H * S * HD];
__device__ float g_att[BS * D];        // 16 MB, attention output [b,s,h*64+d]

// ---------------- kernel 1: h = emb[x] + PE, width_raw = h . Wc + bc ----------------
__global__ void k_embed(const int* __restrict__ x, const float* __restrict__ emb,
                        const float* __restrict__ Wc, const float* __restrict__ bc) {
    int bs = blockIdx.x;
    int s = bs & (S - 1);
    int tok = x[bs];
    const float* e = emb + (size_t)tok * D;
    float* hrow = g_h + (size_t)bs * D;
    const float c = -logf(10000.0f) / (float)D;
    float wsum = 0.f;
    for (int d = threadIdx.x; d < D; d += 256) {
        int i2 = d & ~1;                       // 2*(d/2)
        float dv = expf(c * (float)i2);
        float ang = (float)s * dv;
        float pe = (d & 1) ? cosf(ang) : sinf(ang);
        float hv = e[d] + pe;
        hrow[d] = hv;
        wsum += hv * Wc[d];
    }
    __shared__ float red[256];
    red[threadIdx.x] = wsum;
    __syncthreads();
    for (int off = 128; off > 0; off >>= 1) {
        if (threadIdx.x < off) red[threadIdx.x] += red[threadIdx.x + off];
        __syncthreads();
    }
    if (threadIdx.x == 0) g_w[bs] = red[0] + bc[0];
}

// ---------------- kernel 2: per-batch min-max normalize of width ----------------
__global__ void k_norm() {
    int b = blockIdx.x;
    int t = threadIdx.x;                       // 1024 threads
    float v = g_w[b * S + t];
    float mn = v, mx = v;
    __shared__ float smin[32], smax[32];
    #pragma unroll
    for (int off = 16; off; off >>= 1) {
        mn = fminf(mn, __shfl_xor_sync(0xffffffffu, mn, off));
        mx = fmaxf(mx, __shfl_xor_sync(0xffffffffu, mx, off));
    }
    if ((t & 31) == 0) { smin[t >> 5] = mn; smax[t >> 5] = mx; }
    __syncthreads();
    if (t < 32) {
        mn = smin[t]; mx = smax[t];
        #pragma unroll
        for (int off = 16; off; off >>= 1) {
            mn = fminf(mn, __shfl_xor_sync(0xffffffffu, mn, off));
            mx = fmaxf(mx, __shfl_xor_sync(0xffffffffu, mx, off));
        }
        if (t == 0) { smin[0] = mn; smax[0] = mx; }
    }
    __syncthreads();
    float lo = smin[0], hi = smax[0];
    g_w[b * S + t] = (v - lo) / (hi - lo);
}

// ---------------- kernel 3: mask[b,i,j] ----------------
// idx[i,j] = (S/2-1 - i + j) mod S ; origin piecewise linspace;
// move = (i<S/2) ? (idx>=j) : (idx<j); mask = move * (1 - sigmoid((origin-width)*100))
__global__ void k_mask(float* __restrict__ mout) {
    int i = blockIdx.x, b = blockIdx.y;
    float w = g_w[b * S + i];
    float* mrow = mout + ((size_t)b * S + i) * S;
    bool lower = (i < S / 2);
    for (int j = threadIdx.x; j < S; j += 256) {
        int idx = (S / 2 - 1 - i + j) & (S - 1);
        float origin = (idx < S / 2) ? (1.0f - (float)idx * (1.0f / (float)(S / 2 - 1)))
                                     : ((float)(idx - S / 2) * (1.0f / (float)(S / 2 - 1)));
        bool cmp = (idx >= j);
        bool move = lower ? cmp : !cmp;
        float val = 0.f;
        if (move) {
            float z = (origin - w) * 100.f;
            val = 1.f / (1.f + expf(z));       // == 1 - sigmoid(z)
        }
        mrow[j] = val;
    }
}

// ---------------- kernel 4: QKV ----------------
// q[b,h,s,o] = sum_d h[b,s,h*64+d] * Wq[o,d]   (weights shared across heads)
__global__ void k_qkv(const float* __restrict__ Wq, const float* __restrict__ Wk,
                      const float* __restrict__ Wv) {
    extern __shared__ float sm[];
    float* sW = sm;              // 3 * 4096, transposed: sW[w*4096 + d*64 + o]
    float* sh = sm + 3 * 4096;   // 512
    int tid = threadIdx.x;       // 512
    for (int t = tid; t < HD * HD; t += 512) {
        int o = t >> 6, d = t & 63;
        sW[d * 64 + o]        = Wq[t];
        sW[4096 + d * 64 + o] = Wk[t];
        sW[8192 + d * 64 + o] = Wv[t];
    }
    int head = tid >> 6, o = tid & 63;
    for (int r = 0; r < 8; r++) {
        int bs = blockIdx.x * 8 + r;
        __syncthreads();
        sh[tid] = g_h[(size_t)bs * D + tid];
        __syncthreads();
        const float* hseg = sh + head * HD;
        float aq = 0.f, ak = 0.f, av = 0.f;
        #pragma unroll
        for (int d = 0; d < HD; d++) {
            float hv = hseg[d];
            aq += hv * sW[d * 64 + o];
            ak += hv * sW[4096 + d * 64 + o];
            av += hv * sW[8192 + d * 64 + o];
        }
        int b = bs >> 10, s = bs & (S - 1);
        size_t qi = (((size_t)b * H + head) * S + s) * HD + o;
        g_q[qi] = aq; g_k[qi] = ak; g_v[qi] = av;
    }
}

// ---------------- kernel 5: flash attention with multiplicative mask ----------------
// energy = (q.k) * mask[h,i,j] * SCALE ; masked entries are 0 (NOT -inf) and
// participate in the softmax. One warp per query, 32 queries / block, 64-key tiles.
__global__ void __launch_bounds__(1024) k_attn(const float* __restrict__ mask) {
    extern __shared__ float sm[];
    float* sQ = sm;              // 32*64
    float* sK = sm + 2048;       // 64*65 (padded)
    float* sV = sK + 4160;       // 64*65
    float* sP = sV + 4160;       // 32*64

    int qt = blockIdx.x & 31;
    int bh = blockIdx.x >> 5;
    int h = bh & 7;
    int b = bh >> 3;
    int tid = threadIdx.x;
    int w = tid >> 5, lane = tid & 31;
    int iq = qt * 32 + w;
    size_t base = (size_t)bh * S * HD;

    for (int t = tid; t < 32 * 64; t += 1024)
        sQ[t] = g_q[base + (size_t)qt * 2048 + t];

    const float* mrow = mask + ((size_t)h * S + iq) * S;

    float m = -1e30f, l = 0.f, acc0 = 0.f, acc1 = 0.f;

    for (int kt = 0; kt < S / 64; kt++) {
        __syncthreads();
        for (int t = tid; t < 4096; t += 1024) {
            int r = t >> 6, c = t & 63;
            size_t g = base + (size_t)(kt * 64 + r) * 64 + c;
            sK[r * 65 + c] = g_k[g];
            sV[r * 65 + c] = g_v[g];
        }
        __syncthreads();

        float s0 = 0.f, s1 = 0.f;
        const float* qp  = sQ + w * 64;
        const float* kp0 = sK + lane * 65;
        const float* kp1 = sK + (lane + 32) * 65;
        #pragma unroll
        for (int d = 0; d < 64; d++) {
            float qd = qp[d];
            s0 += qd * kp0[d];
            s1 += qd * kp1[d];
        }
        s0 *= mrow[kt * 64 + lane] * SCALE;
        s1 *= mrow[kt * 64 + lane + 32] * SCALE;

        float tmax = fmaxf(s0, s1);
        #pragma unroll
        for (int off = 16; off; off >>= 1)
            tmax = fmaxf(tmax, __shfl_xor_sync(0xffffffffu, tmax, off));
        float mn = fmaxf(m, tmax);
        float alpha = __expf(m - mn);
        float p0 = __expf(s0 - mn);
        float p1 = __expf(s1 - mn);
        float ls = p0 + p1;
        #pragma unroll
        for (int off = 16; off; off >>= 1)
            ls += __shfl_xor_sync(0xffffffffu, ls, off);
        l = l * alpha + ls;
        m = mn;

        sP[w * 64 + lane] = p0;
        sP[w * 64 + lane + 32] = p1;
        __syncwarp();
        acc0 *= alpha; acc1 *= alpha;
        const float* pp = sP + w * 64;
        #pragma unroll
        for (int j = 0; j < 64; j++) {
            float p = pp[j];
            acc0 += p * sV[j * 65 + lane];
            acc1 += p * sV[j * 65 + lane + 32];
        }
    }
    float inv = 1.f / l;
    size_t o = ((size_t)(b * S + iq)) * D + h * 64 + lane;
    g_att[o] = acc0 * inv;
    g_att[o + 32] = acc1 * inv;
}

// ---------------- kernel 6: out = att @ Wo^T + bo  (M=8192, N=512, K=512) ----------------
#define PBM 128
#define PBN 128
#define PBK 16
#define PLD 130   // padded smem row stride (conflict-free transposed stores)
__global__ void __launch_bounds__(256) k_proj(const float* __restrict__ Wo,
                                              const float* __restrict__ bo,
                                              float* __restrict__ out) {
    __shared__ float As[PBK * PLD];
    __shared__ float Bs[PBK * PLD];
    int m0 = blockIdx.x * PBM;
    int n0 = blockIdx.y * PBN;
    int tid = threadIdx.x;
    int tx = tid & 15, ty = tid >> 4;
    float c[8][8] = {};
    for (int k0 = 0; k0 < D; k0 += PBK) {
        __syncthreads();
        #pragma unroll
        for (int i = 0; i < 8; i++) {
            int idx = tid + i * 256;
            int r = idx >> 4, ck = idx & 15;
            As[ck * PLD + r] = g_att[(size_t)(m0 + r) * D + k0 + ck];
            Bs[ck * PLD + r] = Wo[(size_t)(n0 + r) * D + k0 + ck];
        }
        __syncthreads();
        #pragma unroll
        for (int kk = 0; kk < PBK; kk++) {
            float a[8], bb[8];
            #pragma unroll
            for (int i = 0; i < 8; i++) a[i] = As[kk * PLD + ty + i * 16];
            #pragma unroll
            for (int j = 0; j < 8; j++) bb[j] = Bs[kk * PLD + tx + j * 16];
            #pragma unroll
            for (int i = 0; i < 8; i++)
                #pragma unroll
                for (int j = 0; j < 8; j++)
                    c[i][j] += a[i] * bb[j];
        }
    }
    #pragma unroll
    for (int i = 0; i < 8; i++) {
        int mrow = m0 + ty + i * 16;
        #pragma unroll
        for (int j = 0; j < 8; j++) {
            int n = n0 + tx + j * 16;
            out[(size_t)mrow * D + n] = c[i][j] + bo[n];
        }
    }
}

// ---------------- launch ----------------
extern "C" void kernel_launch(void* const* d_in, const int* in_sizes, int n_in,
                              void* d_out, int out_size) {
    const int*   x   = (const int*)d_in[0];
    const float* emb = (const float*)d_in[1];
    const float* Wq  = (const float*)d_in[2];
    const float* Wk  = (const float*)d_in[3];
    const float* Wv  = (const float*)d_in[4];
    const float* Wo  = (const float*)d_in[5];
    const float* bo  = (const float*)d_in[6];
    const float* Wc  = (const float*)d_in[7];
    const float* bc  = (const float*)d_in[8];
    float* out = (float*)d_out;
    float* maskout = out + (size_t)B * S * D;   // (out, mask) concatenated

    k_embed<<<BS, 256>>>(x, emb, Wc, bc);
    k_norm<<<B, S>>>();
    dim3 mg(S, B);
    k_mask<<<mg, 256>>>(maskout);

    size_t qkv_smem = (3 * 4096 + 512) * sizeof(float);      // 51200 B
    cudaFuncSetAttribute(k_qkv, cudaFuncAttributeMaxDynamicSharedMemorySize, (int)qkv_smem);
    k_qkv<<<BS / 8, 512, qkv_smem>>>(Wq, Wk, Wv);

    size_t attn_smem = (2048 + 4160 + 4160 + 2048) * sizeof(float);  // 49664 B
    cudaFuncSetAttribute(k_attn, cudaFuncAttributeMaxDynamicSharedMemorySize, (int)attn_smem);
    k_attn<<<B * H * (S / 32), 1024, attn_smem>>>(maskout);

    dim3 pg(BS / PBM, D / PBN);
    k_proj<<<pg, 256>>>(Wo, bo, out);
}

// round 2
// speedup vs baseline: 2.0061x; 2.0061x over previous
#include <cuda_runtime.h>
#include <math.h>

#define B 8
#define S 1024
#define D 512
#define H 8
#define HD 64
#define BS (B*S)
#define SCALE 0.044194173824159216f  // 1/sqrt(512)

// ---------------- scratch (static device globals; no allocation) ----------------
__device__ float g_h[BS * D];          // 16 MB  h = emb[x] + pos
__device__ float g_w[BS];              // width (raw -> normalized)
__device__ float g_q[B * H * S * HD];  // 16 MB, layout [b,h,s,d]
__device__ float g_k[B * H * S * HD];
__device__ float g_v[B * H * S * HD];
__device__ float g_att[BS * D];        // 16 MB, attention output [b,s,h*64+d]

// ---------------- kernel 1: h = emb[x] + PE, width_raw = h . Wc + bc ----------------
__global__ void k_embed(const int* __restrict__ x, const float* __restrict__ emb,
                        const float* __restrict__ Wc, const float* __restrict__ bc) {
    int bs = blockIdx.x;
    int s = bs & (S - 1);
    int tok = x[bs];
    const float* e = emb + (size_t)tok * D;
    float* hrow = g_h + (size_t)bs * D;
    const float c = -logf(10000.0f) / (float)D;
    float wsum = 0.f;
    for (int d = threadIdx.x; d < D; d += 256) {
        int i2 = d & ~1;
        float dv = expf(c * (float)i2);
        float ang = (float)s * dv;
        float pe = (d & 1) ? cosf(ang) : sinf(ang);
        float hv = e[d] + pe;
        hrow[d] = hv;
        wsum += hv * Wc[d];
    }
    __shared__ float red[256];
    red[threadIdx.x] = wsum;
    __syncthreads();
    for (int off = 128; off > 0; off >>= 1) {
        if (threadIdx.x < off) red[threadIdx.x] += red[threadIdx.x + off];
        __syncthreads();
    }
    if (threadIdx.x == 0) g_w[bs] = red[0] + bc[0];
}

// ---------------- kernel 2: per-batch min-max normalize of width ----------------
__global__ void k_norm() {
    int b = blockIdx.x;
    int t = threadIdx.x;
    float v = g_w[b * S + t];
    float mn = v, mx = v;
    __shared__ float smin[32], smax[32];
    #pragma unroll
    for (int off = 16; off; off >>= 1) {
        mn = fminf(mn, __shfl_xor_sync(0xffffffffu, mn, off));
        mx = fmaxf(mx, __shfl_xor_sync(0xffffffffu, mx, off));
    }
    if ((t & 31) == 0) { smin[t >> 5] = mn; smax[t >> 5] = mx; }
    __syncthreads();
    if (t < 32) {
        mn = smin[t]; mx = smax[t];
        #pragma unroll
        for (int off = 16; off; off >>= 1) {
            mn = fminf(mn, __shfl_xor_sync(0xffffffffu, mn, off));
            mx = fmaxf(mx, __shfl_xor_sync(0xffffffffu, mx, off));
        }
        if (t == 0) { smin[0] = mn; smax[0] = mx; }
    }
    __syncthreads();
    float lo = smin[0], hi = smax[0];
    g_w[b * S + t] = (v - lo) / (hi - lo);
}

// ---------------- kernel 3: mask[b,i,j] ----------------
__global__ void k_mask(float* __restrict__ mout) {
    int i = blockIdx.x, b = blockIdx.y;
    float w = g_w[b * S + i];
    float* mrow = mout + ((size_t)b * S + i) * S;
    bool lower = (i < S / 2);
    for (int j = threadIdx.x; j < S; j += 256) {
        int idx = (S / 2 - 1 - i + j) & (S - 1);
        float origin = (idx < S / 2) ? (1.0f - (float)idx * (1.0f / (float)(S / 2 - 1)))
                                     : ((float)(idx - S / 2) * (1.0f / (float)(S / 2 - 1)));
        bool cmp = (idx >= j);
        bool move = lower ? cmp : !cmp;
        float val = 0.f;
        if (move) {
            float z = (origin - w) * 100.f;
            val = 1.f / (1.f + expf(z));
        }
        mrow[j] = val;
    }
}

// ---------------- kernel 4: QKV (register-tiled: 4 rows/thread) ----------------
// Block: 32 rows. 512 threads = (head, o). Per 4-row chunk: W read once, 12 FFMA.
__global__ void __launch_bounds__(512) k_qkv(const float* __restrict__ Wq,
                                             const float* __restrict__ Wk,
                                             const float* __restrict__ Wv) {
    extern __shared__ float sm[];
    float* sW = sm;              // 3*4096, transposed [d][o]
    float* sh = sm + 3 * 4096;   // 4 rows * 512
    int tid = threadIdx.x;
    for (int t = tid; t < HD * HD; t += 512) {
        int o = t >> 6, d = t & 63;
        sW[d * 64 + o]        = Wq[t];
        sW[4096 + d * 64 + o] = Wk[t];
        sW[8192 + d * 64 + o] = Wv[t];
    }
    int head = tid >> 6, o = tid & 63;
    int row0 = blockIdx.x * 32;
    for (int ch = 0; ch < 8; ch++) {
        int r0 = row0 + ch * 4;
        __syncthreads();
        #pragma unroll
        for (int t = 0; t < 4; t++) {
            int idx = tid + t * 512;            // 2048 elems
            sh[idx] = g_h[(size_t)(r0 + (idx >> 9)) * D + (idx & 511)];
        }
        __syncthreads();
        float aq[4] = {}, ak[4] = {}, av[4] = {};
        const float* hb = sh + head * HD;
        #pragma unroll 8
        for (int d = 0; d < HD; d++) {
            float wq = sW[d * 64 + o];
            float wk = sW[4096 + d * 64 + o];
            float wv = sW[8192 + d * 64 + o];
            #pragma unroll
            for (int r = 0; r < 4; r++) {
                float hv = hb[r * 512 + d];
                aq[r] += hv * wq;
                ak[r] += hv * wk;
                av[r] += hv * wv;
            }
        }
        #pragma unroll
        for (int r = 0; r < 4; r++) {
            int bs = r0 + r;
            int b = bs >> 10, s = bs & (S - 1);
            size_t qi = (((size_t)b * H + head) * S + s) * HD + o;
            g_q[qi] = aq[r]; g_k[qi] = ak[r]; g_v[qi] = av[r];
        }
    }
}

// ---------------- kernel 5: register-tiled flash attention ----------------
// Block: 128 queries, 64-key tiles. 256 threads as 16x16; each thread owns an
// 8(q)x4(k) energy tile and an 8(q)x4(d) output tile. Mask is multiplicative
// (zeros still enter the softmax).
#define AQ 128
#define AK 64
#define QP 129   // sQT/sPT row pad
#define KP 65    // sKT/sV row pad
__global__ void __launch_bounds__(256, 2) k_attn(const float* __restrict__ mask) {
    extern __shared__ float smx[];
    float* sQT = smx;                    // [d][q] 64 x 128 (pad 129)
    float* sKT = sQT + 64 * QP;          // [d][k] 64 x 64  (pad 65)
    float* sV  = sKT + 64 * KP;          // [k][d] 64 x 64  (pad 65)
    float* sPT = sV  + 64 * KP;          // [k][q] 64 x 128 (pad 129)

    int qt = blockIdx.x & 7;
    int bh = blockIdx.x >> 3;
    int h = bh & 7;
    int b = bh >> 3;
    int tid = threadIdx.x;
    int tx = tid & 15, ty = tid >> 4;
    size_t base = (size_t)bh * S * HD;
    int q0 = qt * AQ;

    // load Q tile transposed: sQT[d][q]
    for (int t = tid; t < AQ * HD; t += 256) {
        int q = t >> 6, d = t & 63;
        sQT[d * QP + q] = g_q[base + (size_t)(q0 + q) * HD + d];
    }

    float m[8], l[8], o[8][4];
    #pragma unroll
    for (int i = 0; i < 8; i++) {
        m[i] = -1e30f; l[i] = 0.f;
        #pragma unroll
        for (int j = 0; j < 4; j++) o[i][j] = 0.f;
    }

    const float* mbase = mask + ((size_t)h * S) * S;

    for (int kt = 0; kt < S / AK; kt++) {
        __syncthreads();
        // load K (transposed) and V (row-major) tiles
        for (int t = tid; t < AK * HD; t += 256) {
            int r = t >> 6, c = t & 63;
            size_t g = base + (size_t)(kt * AK + r) * HD + c;
            sKT[c * KP + r] = g_k[g];
            sV[r * KP + c]  = g_v[g];
        }
        __syncthreads();

        // energy = Q K^T
        float c_[8][4];
        #pragma unroll
        for (int i = 0; i < 8; i++)
            #pragma unroll
            for (int j = 0; j < 4; j++) c_[i][j] = 0.f;
        #pragma unroll 8
        for (int d = 0; d < HD; d++) {
            float a[8], bb[4];
            #pragma unroll
            for (int i = 0; i < 8; i++) a[i] = sQT[d * QP + ty + i * 16];
            #pragma unroll
            for (int j = 0; j < 4; j++) bb[j] = sKT[d * KP + tx + j * 16];
            #pragma unroll
            for (int i = 0; i < 8; i++)
                #pragma unroll
                for (int j = 0; j < 4; j++) c_[i][j] += a[i] * bb[j];
        }

        // mask * scale, online softmax
        #pragma unroll
        for (int i = 0; i < 8; i++) {
            int qg = q0 + ty + i * 16;
            const float* mrow = mbase + (size_t)qg * S + kt * AK;
            float e[4];
            #pragma unroll
            for (int j = 0; j < 4; j++)
                e[j] = c_[i][j] * mrow[tx + j * 16] * SCALE;
            float rm = fmaxf(fmaxf(e[0], e[1]), fmaxf(e[2], e[3]));
            #pragma unroll
            for (int off = 8; off; off >>= 1)
                rm = fmaxf(rm, __shfl_xor_sync(0xffffffffu, rm, off));
            float mn = fmaxf(m[i], rm);
            float alpha = __expf(m[i] - mn);
            float rs = 0.f;
            #pragma unroll
            for (int j = 0; j < 4; j++) {
                e[j] = __expf(e[j] - mn);
                rs += e[j];
            }
            #pragma unroll
            for (int off = 8; off; off >>= 1)
                rs += __shfl_xor_sync(0xffffffffu, rs, off);
            l[i] = l[i] * alpha + rs;
            m[i] = mn;
            #pragma unroll
            for (int j = 0; j < 4; j++) {
                o[i][j] *= alpha;
                sPT[(tx + j * 16) * QP + ty + i * 16] = e[j];
            }
        }
        __syncthreads();

        // out += P V
        #pragma unroll 8
        for (int k = 0; k < AK; k++) {
            float a[8], bb[4];
            #pragma unroll
            for (int i = 0; i < 8; i++) a[i] = sPT[k * QP + ty + i * 16];
            #pragma unroll
            for (int j = 0; j < 4; j++) bb[j] = sV[k * KP + tx + j * 16];
            #pragma unroll
            for (int i = 0; i < 8; i++)
                #pragma unroll
                for (int j = 0; j < 4; j++) o[i][j] += a[i] * bb[j];
        }
    }

    #pragma unroll
    for (int i = 0; i < 8; i++) {
        float inv = 1.f / l[i];
        int qg = q0 + ty + i * 16;
        size_t ob = ((size_t)(b * S + qg)) * D + h * 64;
        #pragma unroll
        for (int j = 0; j < 4; j++)
            g_att[ob + tx + j * 16] = o[i][j] * inv;
    }
}

// ---------------- kernel 6: out = att @ Wo^T + bo ----------------
#define PBM 128
#define PBN 128
#define PBK 16
#define PLD 130
__global__ void __launch_bounds__(256) k_proj(const float* __restrict__ Wo,
                                              const float* __restrict__ bo,
                                              float* __restrict__ out) {
    __shared__ float As[PBK * PLD];
    __shared__ float Bs[PBK * PLD];
    int m0 = blockIdx.x * PBM;
    int n0 = blockIdx.y * PBN;
    int tid = threadIdx.x;
    int tx = tid & 15, ty = tid >> 4;
    float c[8][8] = {};
    for (int k0 = 0; k0 < D; k0 += PBK) {
        __syncthreads();
        #pragma unroll
        for (int i = 0; i < 8; i++) {
            int idx = tid + i * 256;
            int r = idx >> 4, ck = idx & 15;
            As[ck * PLD + r] = g_att[(size_t)(m0 + r) * D + k0 + ck];
            Bs[ck * PLD + r] = Wo[(size_t)(n0 + r) * D + k0 + ck];
        }
        __syncthreads();
        #pragma unroll
        for (int kk = 0; kk < PBK; kk++) {
            float a[8], bb[8];
            #pragma unroll
            for (int i = 0; i < 8; i++) a[i] = As[kk * PLD + ty + i * 16];
            #pragma unroll
            for (int j = 0; j < 8; j++) bb[j] = Bs[kk * PLD + tx + j * 16];
            #pragma unroll
            for (int i = 0; i < 8; i++)
                #pragma unroll
                for (int j = 0; j < 8; j++)
                    c[i][j] += a[i] * bb[j];
        }
    }
    #pragma unroll
    for (int i = 0; i < 8; i++) {
        int mrow = m0 + ty + i * 16;
        #pragma unroll
        for (int j = 0; j < 8; j++) {
            int n = n0 + tx + j * 16;
            out[(size_t)mrow * D + n] = c[i][j] + bo[n];
        }
    }
}

// ---------------- launch ----------------
extern "C" void kernel_launch(void* const* d_in, const int* in_sizes, int n_in,
                              void* d_out, int out_size) {
    const int*   x   = (const int*)d_in[0];
    const float* emb = (const float*)d_in[1];
    const float* Wq  = (const float*)d_in[2];
    const float* Wk  = (const float*)d_in[3];
    const float* Wv  = (const float*)d_in[4];
    const float* Wo  = (const float*)d_in[5];
    const float* bo  = (const float*)d_in[6];
    const float* Wc  = (const float*)d_in[7];
    const float* bc  = (const float*)d_in[8];
    float* out = (float*)d_out;
    float* maskout = out + (size_t)B * S * D;

    k_embed<<<BS, 256>>>(x, emb, Wc, bc);
    k_norm<<<B, S>>>();
    dim3 mg(S, B);
    k_mask<<<mg, 256>>>(maskout);

    size_t qkv_smem = (3 * 4096 + 4 * 512) * sizeof(float);   // 57344 B
    cudaFuncSetAttribute(k_qkv, cudaFuncAttributeMaxDynamicSharedMemorySize, (int)qkv_smem);
    k_qkv<<<BS / 32, 512, qkv_smem>>>(Wq, Wk, Wv);

    size_t attn_smem = (64 * QP + 64 * KP + 64 * KP + 64 * QP) * sizeof(float);  // 99328 B
    cudaFuncSetAttribute(k_attn, cudaFuncAttributeMaxDynamicSharedMemorySize, (int)attn_smem);
    k_attn<<<B * H * (S / AQ), 256, attn_smem>>>(maskout);

    dim3 pg(BS / PBM, D / PBN);
    k_proj<<<pg, 256>>>(Wo, bo, out);
}

// round 3
// speedup vs baseline: 3.5797x; 1.7844x over previous
#include <cuda_runtime.h>
#include <math.h>

#define B 8
#define S 1024
#define D 512
#define H 8
#define HD 64
#define BS (B*S)
#define SCALE 0.044194173824159216f  // 1/sqrt(512)

// ---------------- scratch (static device globals; no allocation) ----------------
__device__ float g_h[BS * D];
__device__ float g_w[BS];
__device__ float g_q[B * H * S * HD];  // [b,h,s,d]
__device__ float g_k[B * H * S * HD];
__device__ float g_v[B * H * S * HD];
__device__ float g_att[BS * D];

// ---------------- helpers ----------------
__device__ __forceinline__ unsigned f2tf(float f) {
    unsigned u;
    asm("cvt.rna.tf32.f32 %0, %1;" : "=r"(u) : "f"(f));
    return u;
}
__device__ __forceinline__ void mma_tf32(float d[4], const unsigned a[4],
                                         unsigned b0, unsigned b1) {
    asm("mma.sync.aligned.m16n8k8.row.col.f32.tf32.tf32.f32 "
        "{%0,%1,%2,%3}, {%4,%5,%6,%7}, {%8,%9}, {%0,%1,%2,%3};"
        : "+f"(d[0]), "+f"(d[1]), "+f"(d[2]), "+f"(d[3])
        : "r"(a[0]), "r"(a[1]), "r"(a[2]), "r"(a[3]), "r"(b0), "r"(b1));
}

// ---------------- kernel 1: h = emb[x] + PE, width_raw = h . Wc + bc ----------------
__global__ void k_embed(const int* __restrict__ x, const float* __restrict__ emb,
                        const float* __restrict__ Wc, const float* __restrict__ bc) {
    int bs = blockIdx.x;
    int s = bs & (S - 1);
    int tok = x[bs];
    const float* e = emb + (size_t)tok * D;
    float* hrow = g_h + (size_t)bs * D;
    const float c = -logf(10000.0f) / (float)D;
    float wsum = 0.f;
    for (int d = threadIdx.x; d < D; d += 256) {
        int i2 = d & ~1;
        float dv = expf(c * (float)i2);
        float ang = (float)s * dv;
        float pe = (d & 1) ? cosf(ang) : sinf(ang);
        float hv = e[d] + pe;
        hrow[d] = hv;
        wsum += hv * Wc[d];
    }
    __shared__ float red[256];
    red[threadIdx.x] = wsum;
    __syncthreads();
    for (int off = 128; off > 0; off >>= 1) {
        if (threadIdx.x < off) red[threadIdx.x] += red[threadIdx.x + off];
        __syncthreads();
    }
    if (threadIdx.x == 0) g_w[bs] = red[0] + bc[0];
}

// ---------------- kernel 2: per-batch min-max normalize ----------------
__global__ void k_norm() {
    int b = blockIdx.x;
    int t = threadIdx.x;
    float v = g_w[b * S + t];
    float mn = v, mx = v;
    __shared__ float smin[32], smax[32];
    #pragma unroll
    for (int off = 16; off; off >>= 1) {
        mn = fminf(mn, __shfl_xor_sync(0xffffffffu, mn, off));
        mx = fmaxf(mx, __shfl_xor_sync(0xffffffffu, mx, off));
    }
    if ((t & 31) == 0) { smin[t >> 5] = mn; smax[t >> 5] = mx; }
    __syncthreads();
    if (t < 32) {
        mn = smin[t]; mx = smax[t];
        #pragma unroll
        for (int off = 16; off; off >>= 1) {
            mn = fminf(mn, __shfl_xor_sync(0xffffffffu, mn, off));
            mx = fmaxf(mx, __shfl_xor_sync(0xffffffffu, mx, off));
        }
        if (t == 0) { smin[0] = mn; smax[0] = mx; }
    }
    __syncthreads();
    float lo = smin[0], hi = smax[0];
    g_w[b * S + t] = (v - lo) / (hi - lo);
}

// ---------------- kernel 3: mask ----------------
__global__ void k_mask(float* __restrict__ mout) {
    int i = blockIdx.x, b = blockIdx.y;
    float w = g_w[b * S + i];
    float* mrow = mout + ((size_t)b * S + i) * S;
    bool lower = (i < S / 2);
    for (int j = threadIdx.x; j < S; j += 256) {
        int idx = (S / 2 - 1 - i + j) & (S - 1);
        float origin = (idx < S / 2) ? (1.0f - (float)idx * (1.0f / (float)(S / 2 - 1)))
                                     : ((float)(idx - S / 2) * (1.0f / (float)(S / 2 - 1)));
        bool cmp = (idx >= j);
        bool move = lower ? cmp : !cmp;
        float val = 0.f;
        if (move) {
            float z = (origin - w) * 100.f;
            val = 1.f / (1.f + expf(z));
        }
        mrow[j] = val;
    }
}

// ---------------- kernel 4: QKV (register-tiled) ----------------
__global__ void __launch_bounds__(512) k_qkv(const float* __restrict__ Wq,
                                             const float* __restrict__ Wk,
                                             const float* __restrict__ Wv) {
    extern __shared__ float sm[];
    float* sW = sm;
    float* sh = sm + 3 * 4096;
    int tid = threadIdx.x;
    for (int t = tid; t < HD * HD; t += 512) {
        int o = t >> 6, d = t & 63;
        sW[d * 64 + o]        = Wq[t];
        sW[4096 + d * 64 + o] = Wk[t];
        sW[8192 + d * 64 + o] = Wv[t];
    }
    int head = tid >> 6, o = tid & 63;
    int row0 = blockIdx.x * 32;
    for (int ch = 0; ch < 8; ch++) {
        int r0 = row0 + ch * 4;
        __syncthreads();
        #pragma unroll
        for (int t = 0; t < 4; t++) {
            int idx = tid + t * 512;
            sh[idx] = g_h[(size_t)(r0 + (idx >> 9)) * D + (idx & 511)];
        }
        __syncthreads();
        float aq[4] = {}, ak[4] = {}, av[4] = {};
        const float* hb = sh + head * HD;
        #pragma unroll 8
        for (int d = 0; d < HD; d++) {
            float wq = sW[d * 64 + o];
            float wk = sW[4096 + d * 64 + o];
            float wv = sW[8192 + d * 64 + o];
            #pragma unroll
            for (int r = 0; r < 4; r++) {
                float hv = hb[r * 512 + d];
                aq[r] += hv * wq;
                ak[r] += hv * wk;
                av[r] += hv * wv;
            }
        }
        #pragma unroll
        for (int r = 0; r < 4; r++) {
            int bs = r0 + r;
            int b = bs >> 10, s = bs & (S - 1);
            size_t qi = (((size_t)b * H + head) * S + s) * HD + o;
            g_q[qi] = aq[r]; g_k[qi] = ak[r]; g_v[qi] = av[r];
        }
    }
}

// ---------------- kernel 5: tensor-core (tf32 mma.sync) flash attention ----------------
// Block: 128 queries, 8 warps (16 q each), 64-key tiles. Q fragments in regs.
// K smem [key][d] pad 68 (banks 4r+c distinct), V smem [key][d] pad 72 (8c+r),
// P warp-private smem [q][key] pad 68. Mask read direct from global in frag layout.
#define KPAD 68
#define VPAD 72
#define PPAD 68
__global__ void __launch_bounds__(256, 2) k_attn(const float* __restrict__ mask) {
    extern __shared__ float smx[];
    float* sK = smx;                     // 64*68
    float* sV = sK + 64 * KPAD;          // 64*72
    float* sP = sV + 64 * VPAD;          // 128*68

    int tid = threadIdx.x;
    int w = tid >> 5, lane = tid & 31;
    int r4 = lane >> 2, c4 = lane & 3;
    int qt = blockIdx.x & 7;
    int bh = blockIdx.x >> 3;
    int h = bh & 7, b = bh >> 3;
    size_t base = (size_t)bh * S * HD;
    int qw = qt * 128 + w * 16;

    // Q fragments (tf32), rows qw+r4 / qw+r4+8
    unsigned qa[8][4];
    {
        const float* qb = g_q + base + (size_t)qw * HD;
        #pragma unroll
        for (int kk = 0; kk < 8; kk++) {
            qa[kk][0] = f2tf(qb[(size_t)r4 * 64 + kk * 8 + c4]);
            qa[kk][1] = f2tf(qb[(size_t)(r4 + 8) * 64 + kk * 8 + c4]);
            qa[kk][2] = f2tf(qb[(size_t)r4 * 64 + kk * 8 + c4 + 4]);
            qa[kk][3] = f2tf(qb[(size_t)(r4 + 8) * 64 + kk * 8 + c4 + 4]);
        }
    }

    float o[8][4];
    #pragma unroll
    for (int nt = 0; nt < 8; nt++)
        #pragma unroll
        for (int j = 0; j < 4; j++) o[nt][j] = 0.f;
    float m0 = -1e30f, m1 = -1e30f, l0 = 0.f, l1 = 0.f;

    const float* mrow0 = mask + ((size_t)h * S + qw + r4) * S;
    const float* mrow1 = mrow0 + (size_t)8 * S;
    float* sPw = sP + w * 16 * PPAD;

    for (int kt = 0; kt < S / 64; kt++) {
        __syncthreads();
        // stage K,V tiles (tf32-converted)
        const float* gk = g_k + base + (size_t)kt * 64 * 64;
        const float* gv = g_v + base + (size_t)kt * 64 * 64;
        #pragma unroll 4
        for (int i = tid; i < 64 * 64; i += 256) {
            int key = i >> 6, d = i & 63;
            sK[key * KPAD + d] = __uint_as_float(f2tf(gk[i]));
            sV[key * VPAD + d] = __uint_as_float(f2tf(gv[i]));
        }
        __syncthreads();

        // energy = Q K^T   (e[nt]: rows r4/r4+8, key cols nt*8 + 2c4,2c4+1)
        float e[8][4];
        #pragma unroll
        for (int nt = 0; nt < 8; nt++) {
            #pragma unroll
            for (int j = 0; j < 4; j++) e[nt][j] = 0.f;
            #pragma unroll
            for (int kk = 0; kk < 8; kk++) {
                unsigned b0 = __float_as_uint(sK[(nt * 8 + r4) * KPAD + kk * 8 + c4]);
                unsigned b1 = __float_as_uint(sK[(nt * 8 + r4) * KPAD + kk * 8 + c4 + 4]);
                mma_tf32(e[nt], qa[kk], b0, b1);
            }
        }

        // mask * scale
        int kb = kt * 64;
        #pragma unroll
        for (int nt = 0; nt < 8; nt++) {
            float2 mm0 = *(const float2*)&mrow0[kb + nt * 8 + 2 * c4];
            float2 mm1 = *(const float2*)&mrow1[kb + nt * 8 + 2 * c4];
            e[nt][0] *= mm0.x * SCALE;
            e[nt][1] *= mm0.y * SCALE;
            e[nt][2] *= mm1.x * SCALE;
            e[nt][3] *= mm1.y * SCALE;
        }

        // online softmax (rows r4 and r4+8; reduce across quad lanes)
        float rm0 = -1e30f, rm1 = -1e30f;
        #pragma unroll
        for (int nt = 0; nt < 8; nt++) {
            rm0 = fmaxf(rm0, fmaxf(e[nt][0], e[nt][1]));
            rm1 = fmaxf(rm1, fmaxf(e[nt][2], e[nt][3]));
        }
        rm0 = fmaxf(rm0, __shfl_xor_sync(0xffffffffu, rm0, 1));
        rm0 = fmaxf(rm0, __shfl_xor_sync(0xffffffffu, rm0, 2));
        rm1 = fmaxf(rm1, __shfl_xor_sync(0xffffffffu, rm1, 1));
        rm1 = fmaxf(rm1, __shfl_xor_sync(0xffffffffu, rm1, 2));
        float mn0 = fmaxf(m0, rm0), mn1 = fmaxf(m1, rm1);
        float a0 = __expf(m0 - mn0), a1 = __expf(m1 - mn1);
        float rs0 = 0.f, rs1 = 0.f;
        #pragma unroll
        for (int nt = 0; nt < 8; nt++) {
            e[nt][0] = __expf(e[nt][0] - mn0);
            e[nt][1] = __expf(e[nt][1] - mn0);
            e[nt][2] = __expf(e[nt][2] - mn1);
            e[nt][3] = __expf(e[nt][3] - mn1);
            rs0 += e[nt][0] + e[nt][1];
            rs1 += e[nt][2] + e[nt][3];
        }
        rs0 += __shfl_xor_sync(0xffffffffu, rs0, 1);
        rs0 += __shfl_xor_sync(0xffffffffu, rs0, 2);
        rs1 += __shfl_xor_sync(0xffffffffu, rs1, 1);
        rs1 += __shfl_xor_sync(0xffffffffu, rs1, 2);
        l0 = l0 * a0 + rs0;
        l1 = l1 * a1 + rs1;
        m0 = mn0; m1 = mn1;

        // write P (tf32) to warp-private smem; rescale O
        #pragma unroll
        for (int nt = 0; nt < 8; nt++) {
            float2 p0, p1;
            p0.x = __uint_as_float(f2tf(e[nt][0]));
            p0.y = __uint_as_float(f2tf(e[nt][1]));
            p1.x = __uint_as_float(f2tf(e[nt][2]));
            p1.y = __uint_as_float(f2tf(e[nt][3]));
            *(float2*)&sPw[r4 * PPAD + nt * 8 + 2 * c4] = p0;
            *(float2*)&sPw[(r4 + 8) * PPAD + nt * 8 + 2 * c4] = p1;
            o[nt][0] *= a0; o[nt][1] *= a0;
            o[nt][2] *= a1; o[nt][3] *= a1;
        }
        __syncwarp();

        // O += P V
        #pragma unroll
        for (int kk = 0; kk < 8; kk++) {
            unsigned pa[4];
            pa[0] = __float_as_uint(sPw[r4 * PPAD + kk * 8 + c4]);
            pa[1] = __float_as_uint(sPw[(r4 + 8) * PPAD + kk * 8 + c4]);
            pa[2] = __float_as_uint(sPw[r4 * PPAD + kk * 8 + c4 + 4]);
            pa[3] = __float_as_uint(sPw[(r4 + 8) * PPAD + kk * 8 + c4 + 4]);
            #pragma unroll
            for (int nt = 0; nt < 8; nt++) {
                unsigned b0 = __float_as_uint(sV[(kk * 8 + c4) * VPAD + nt * 8 + r4]);
                unsigned b1 = __float_as_uint(sV[(kk * 8 + c4 + 4) * VPAD + nt * 8 + r4]);
                mma_tf32(o[nt], pa, b0, b1);
            }
        }
        __syncwarp();
    }

    float inv0 = 1.f / l0, inv1 = 1.f / l1;
    size_t ob0 = ((size_t)(b * S + qw + r4)) * D + h * 64;
    size_t ob1 = ((size_t)(b * S + qw + r4 + 8)) * D + h * 64;
    #pragma unroll
    for (int nt = 0; nt < 8; nt++) {
        float2 v0, v1;
        v0.x = o[nt][0] * inv0; v0.y = o[nt][1] * inv0;
        v1.x = o[nt][2] * inv1; v1.y = o[nt][3] * inv1;
        *(float2*)&g_att[ob0 + nt * 8 + 2 * c4] = v0;
        *(float2*)&g_att[ob1 + nt * 8 + 2 * c4] = v1;
    }
}

// ---------------- kernel 6: out = att @ Wo^T + bo ----------------
#define PBM 128
#define PBN 128
#define PBK 16
#define PLD 130
__global__ void __launch_bounds__(256) k_proj(const float* __restrict__ Wo,
                                              const float* __restrict__ bo,
                                              float* __restrict__ out) {
    __shared__ float As[PBK * PLD];
    __shared__ float Bs[PBK * PLD];
    int m0 = blockIdx.x * PBM;
    int n0 = blockIdx.y * PBN;
    int tid = threadIdx.x;
    int tx = tid & 15, ty = tid >> 4;
    float c[8][8] = {};
    for (int k0 = 0; k0 < D; k0 += PBK) {
        __syncthreads();
        #pragma unroll
        for (int i = 0; i < 8; i++) {
            int idx = tid + i * 256;
            int r = idx >> 4, ck = idx & 15;
            As[ck * PLD + r] = g_att[(size_t)(m0 + r) * D + k0 + ck];
            Bs[ck * PLD + r] = Wo[(size_t)(n0 + r) * D + k0 + ck];
        }
        __syncthreads();
        #pragma unroll
        for (int kk = 0; kk < PBK; kk++) {
            float a[8], bb[8];
            #pragma unroll
            for (int i = 0; i < 8; i++) a[i] = As[kk * PLD + ty + i * 16];
            #pragma unroll
            for (int j = 0; j < 8; j++) bb[j] = Bs[kk * PLD + tx + j * 16];
            #pragma unroll
            for (int i = 0; i < 8; i++)
                #pragma unroll
                for (int j = 0; j < 8; j++)
                    c[i][j] += a[i] * bb[j];
        }
    }
    #pragma unroll
    for (int i = 0; i < 8; i++) {
        int mrow = m0 + ty + i * 16;
        #pragma unroll
        for (int j = 0; j < 8; j++) {
            int n = n0 + tx + j * 16;
            out[(size_t)mrow * D + n] = c[i][j] + bo[n];
        }
    }
}

// ---------------- launch ----------------
extern "C" void kernel_launch(void* const* d_in, const int* in_sizes, int n_in,
                              void* d_out, int out_size) {
    const int*   x   = (const int*)d_in[0];
    const float* emb = (const float*)d_in[1];
    const float* Wq  = (const float*)d_in[2];
    const float* Wk  = (const float*)d_in[3];
    const float* Wv  = (const float*)d_in[4];
    const float* Wo  = (const float*)d_in[5];
    const float* bo  = (const float*)d_in[6];
    const float* Wc  = (const float*)d_in[7];
    const float* bc  = (const float*)d_in[8];
    float* out = (float*)d_out;
    float* maskout = out + (size_t)B * S * D;

    k_embed<<<BS, 256>>>(x, emb, Wc, bc);
    k_norm<<<B, S>>>();
    dim3 mg(S, B);
    k_mask<<<mg, 256>>>(maskout);

    size_t qkv_smem = (3 * 4096 + 4 * 512) * sizeof(float);
    cudaFuncSetAttribute(k_qkv, cudaFuncAttributeMaxDynamicSharedMemorySize, (int)qkv_smem);
    k_qkv<<<BS / 32, 512, qkv_smem>>>(Wq, Wk, Wv);

    size_t attn_smem = (64 * KPAD + 64 * VPAD + 128 * PPAD) * sizeof(float);  // 70656 B
    cudaFuncSetAttribute(k_attn, cudaFuncAttributeMaxDynamicSharedMemorySize, (int)attn_smem);
    k_attn<<<B * H * (S / 128), 256, attn_smem>>>(maskout);

    dim3 pg(BS / PBM, D / PBN);
    k_proj<<<pg, 256>>>(Wo, bo, out);
}

// round 4
// speedup vs baseline: 5.0570x; 1.4127x over previous
#include <cuda_runtime.h>
#include <math.h>

#define B 8
#define S 1024
#define D 512
#define H 8
#define HD 64
#define BS (B*S)
#define SCALE 0.044194173824159216f  // 1/sqrt(512)

// ---------------- scratch (static device globals; no allocation) ----------------
__device__ float g_h[BS * D];
__device__ float g_w[BS];
__device__ float g_q[B * H * S * HD];  // [b,h,s,d]
__device__ float g_k[B * H * S * HD];
__device__ float g_v[B * H * S * HD];
__device__ float g_att[BS * D];

// ---------------- helpers ----------------
__device__ __forceinline__ unsigned f2tf(float f) {
    unsigned u;
    asm("cvt.rna.tf32.f32 %0, %1;" : "=r"(u) : "f"(f));
    return u;
}
__device__ __forceinline__ void mma_tf32(float d[4], const unsigned a[4],
                                         unsigned b0, unsigned b1) {
    asm("mma.sync.aligned.m16n8k8.row.col.f32.tf32.tf32.f32 "
        "{%0,%1,%2,%3}, {%4,%5,%6,%7}, {%8,%9}, {%0,%1,%2,%3};"
        : "+f"(d[0]), "+f"(d[1]), "+f"(d[2]), "+f"(d[3])
        : "r"(a[0]), "r"(a[1]), "r"(a[2]), "r"(a[3]), "r"(b0), "r"(b1));
}

// ---------------- kernel 1: h = emb[x] + PE, width_raw = h . Wc + bc ----------------
__global__ void k_embed(const int* __restrict__ x, const float* __restrict__ emb,
                        const float* __restrict__ Wc, const float* __restrict__ bc) {
    int bs = blockIdx.x;
    int s = bs & (S - 1);
    int tok = x[bs];
    const float* e = emb + (size_t)tok * D;
    float* hrow = g_h + (size_t)bs * D;
    const float c = -logf(10000.0f) / (float)D;
    float wsum = 0.f;
    for (int d = threadIdx.x; d < D; d += 256) {
        int i2 = d & ~1;
        float dv = expf(c * (float)i2);
        float ang = (float)s * dv;
        float pe = (d & 1) ? cosf(ang) : sinf(ang);
        float hv = e[d] + pe;
        hrow[d] = hv;
        wsum += hv * Wc[d];
    }
    __shared__ float red[256];
    red[threadIdx.x] = wsum;
    __syncthreads();
    for (int off = 128; off > 0; off >>= 1) {
        if (threadIdx.x < off) red[threadIdx.x] += red[threadIdx.x + off];
        __syncthreads();
    }
    if (threadIdx.x == 0) g_w[bs] = red[0] + bc[0];
}

// ---------------- kernel 2: per-batch min-max normalize ----------------
__global__ void k_norm() {
    int b = blockIdx.x;
    int t = threadIdx.x;
    float v = g_w[b * S + t];
    float mn = v, mx = v;
    __shared__ float smin[32], smax[32];
    #pragma unroll
    for (int off = 16; off; off >>= 1) {
        mn = fminf(mn, __shfl_xor_sync(0xffffffffu, mn, off));
        mx = fmaxf(mx, __shfl_xor_sync(0xffffffffu, mx, off));
    }
    if ((t & 31) == 0) { smin[t >> 5] = mn; smax[t >> 5] = mx; }
    __syncthreads();
    if (t < 32) {
        mn = smin[t]; mx = smax[t];
        #pragma unroll
        for (int off = 16; off; off >>= 1) {
            mn = fminf(mn, __shfl_xor_sync(0xffffffffu, mn, off));
            mx = fmaxf(mx, __shfl_xor_sync(0xffffffffu, mx, off));
        }
        if (t == 0) { smin[0] = mn; smax[0] = mx; }
    }
    __syncthreads();
    float lo = smin[0], hi = smax[0];
    g_w[b * S + t] = (v - lo) / (hi - lo);
}

// ---------------- kernel 3: mask ----------------
__global__ void k_mask(float* __restrict__ mout) {
    int i = blockIdx.x, b = blockIdx.y;
    float w = g_w[b * S + i];
    float* mrow = mout + ((size_t)b * S + i) * S;
    bool lower = (i < S / 2);
    for (int j = threadIdx.x; j < S; j += 256) {
        int idx = (S / 2 - 1 - i + j) & (S - 1);
        float origin = (idx < S / 2) ? (1.0f - (float)idx * (1.0f / (float)(S / 2 - 1)))
                                     : ((float)(idx - S / 2) * (1.0f / (float)(S / 2 - 1)));
        bool cmp = (idx >= j);
        bool move = lower ? cmp : !cmp;
        float val = 0.f;
        if (move) {
            float z = (origin - w) * 100.f;
            val = 1.f / (1.f + expf(z));
        }
        mrow[j] = val;
    }
}

// ---------------- kernel 4: QKV via tf32 mma ----------------
// Grid: (row-blocks of 128, head). Stage h slice [128x64] + Wq/Wk/Wv [64x64]
// (all tf32, pad 68). 8 warps x 16 rows. Q/K/V computed sequentially, shared
// A fragments, one accumulator set.
#define GP 68
__global__ void __launch_bounds__(256) k_qkv(const float* __restrict__ Wq,
                                             const float* __restrict__ Wk,
                                             const float* __restrict__ Wv) {
    extern __shared__ float sm[];
    float* sA = sm;               // 128 x 68
    float* sB = sm + 128 * GP;    // 3 x 64 x 68
    int tid = threadIdx.x;
    int w = tid >> 5, lane = tid & 31;
    int r4 = lane >> 2, c4 = lane & 3;
    int m0 = blockIdx.x * 128;
    int h = blockIdx.y;

    // stage A: h[m0+r][h*64+c], r<128, c<64  (float4 + tf32)
    #pragma unroll
    for (int t = 0; t < 8; t++) {
        int idx = (tid + t * 256) * 4;          // 8192 elems
        int r = idx >> 6, c = idx & 63;
        float4 v = *(const float4*)&g_h[(size_t)(m0 + r) * D + h * 64 + c];
        unsigned u0 = f2tf(v.x), u1 = f2tf(v.y), u2 = f2tf(v.z), u3 = f2tf(v.w);
        uint4 uu = make_uint4(u0, u1, u2, u3);
        *(uint4*)&sA[r * GP + c] = uu;
    }
    // stage weights (3 x 4096)
    const float* Ws[3] = {Wq, Wk, Wv};
    #pragma unroll
    for (int wi = 0; wi < 3; wi++) {
        #pragma unroll
        for (int t = 0; t < 4; t++) {
            int idx = (tid + t * 256) * 4;
            int r = idx >> 6, c = idx & 63;
            float4 v = *(const float4*)&Ws[wi][(size_t)r * 64 + c];
            uint4 uu = make_uint4(f2tf(v.x), f2tf(v.y), f2tf(v.z), f2tf(v.w));
            *(uint4*)&sB[(wi * 64 + r) * GP + c] = uu;
        }
    }
    __syncthreads();

    // A fragments for this warp's 16 rows
    const float* Aw = sA + (w * 16) * GP;
    unsigned af[8][4];
    #pragma unroll
    for (int kk = 0; kk < 8; kk++) {
        af[kk][0] = __float_as_uint(Aw[r4 * GP + kk * 8 + c4]);
        af[kk][1] = __float_as_uint(Aw[(r4 + 8) * GP + kk * 8 + c4]);
        af[kk][2] = __float_as_uint(Aw[r4 * GP + kk * 8 + c4 + 4]);
        af[kk][3] = __float_as_uint(Aw[(r4 + 8) * GP + kk * 8 + c4 + 4]);
    }

    int row0 = m0 + w * 16 + r4;
    float* outs[3] = {g_q, g_k, g_v};
    #pragma unroll
    for (int wi = 0; wi < 3; wi++) {
        float acc[8][4];
        #pragma unroll
        for (int nt = 0; nt < 8; nt++) {
            #pragma unroll
            for (int j = 0; j < 4; j++) acc[nt][j] = 0.f;
            #pragma unroll
            for (int kk = 0; kk < 8; kk++) {
                unsigned b0 = __float_as_uint(sB[(wi * 64 + nt * 8 + r4) * GP + kk * 8 + c4]);
                unsigned b1 = __float_as_uint(sB[(wi * 64 + nt * 8 + r4) * GP + kk * 8 + c4 + 4]);
                mma_tf32(acc[nt], af[kk], b0, b1);
            }
        }
        // store: rows row0, row0+8 ; q layout [b,h,s,o]
        int b0r = row0 >> 10, s0 = row0 & (S - 1);
        int b1r = (row0 + 8) >> 10, s1 = (row0 + 8) & (S - 1);
        size_t q0 = (((size_t)b0r * H + h) * S + s0) * HD;
        size_t q1 = (((size_t)b1r * H + h) * S + s1) * HD;
        float* op = outs[wi];
        #pragma unroll
        for (int nt = 0; nt < 8; nt++) {
            float2 v0, v1;
            v0.x = acc[nt][0]; v0.y = acc[nt][1];
            v1.x = acc[nt][2]; v1.y = acc[nt][3];
            *(float2*)&op[q0 + nt * 8 + 2 * c4] = v0;
            *(float2*)&op[q1 + nt * 8 + 2 * c4] = v1;
        }
    }
}

// ---------------- kernel 5: tensor-core (tf32 mma.sync) flash attention ----------------
#define KPAD 68
#define VPAD 72
#define PPAD 68
__global__ void __launch_bounds__(256, 2) k_attn(const float* __restrict__ mask) {
    extern __shared__ float smx[];
    float* sK = smx;                     // 64*68
    float* sV = sK + 64 * KPAD;          // 64*72
    float* sP = sV + 64 * VPAD;          // 128*68

    int tid = threadIdx.x;
    int w = tid >> 5, lane = tid & 31;
    int r4 = lane >> 2, c4 = lane & 3;
    int qt = blockIdx.x & 7;
    int bh = blockIdx.x >> 3;
    int h = bh & 7, b = bh >> 3;
    size_t base = (size_t)bh * S * HD;
    int qw = qt * 128 + w * 16;

    unsigned qa[8][4];
    {
        const float* qb = g_q + base + (size_t)qw * HD;
        #pragma unroll
        for (int kk = 0; kk < 8; kk++) {
            qa[kk][0] = f2tf(qb[(size_t)r4 * 64 + kk * 8 + c4]);
            qa[kk][1] = f2tf(qb[(size_t)(r4 + 8) * 64 + kk * 8 + c4]);
            qa[kk][2] = f2tf(qb[(size_t)r4 * 64 + kk * 8 + c4 + 4]);
            qa[kk][3] = f2tf(qb[(size_t)(r4 + 8) * 64 + kk * 8 + c4 + 4]);
        }
    }

    float o[8][4];
    #pragma unroll
    for (int nt = 0; nt < 8; nt++)
        #pragma unroll
        for (int j = 0; j < 4; j++) o[nt][j] = 0.f;
    float m0 = -1e30f, m1 = -1e30f, l0 = 0.f, l1 = 0.f;

    const float* mrow0 = mask + ((size_t)h * S + qw + r4) * S;
    const float* mrow1 = mrow0 + (size_t)8 * S;
    float* sPw = sP + w * 16 * PPAD;

    for (int kt = 0; kt < S / 64; kt++) {
        __syncthreads();
        const float* gk = g_k + base + (size_t)kt * 64 * 64;
        const float* gv = g_v + base + (size_t)kt * 64 * 64;
        #pragma unroll 4
        for (int i = tid; i < 64 * 64; i += 256) {
            int key = i >> 6, d = i & 63;
            sK[key * KPAD + d] = __uint_as_float(f2tf(gk[i]));
            sV[key * VPAD + d] = __uint_as_float(f2tf(gv[i]));
        }
        __syncthreads();

        float e[8][4];
        #pragma unroll
        for (int nt = 0; nt < 8; nt++) {
            #pragma unroll
            for (int j = 0; j < 4; j++) e[nt][j] = 0.f;
            #pragma unroll
            for (int kk = 0; kk < 8; kk++) {
                unsigned b0 = __float_as_uint(sK[(nt * 8 + r4) * KPAD + kk * 8 + c4]);
                unsigned b1 = __float_as_uint(sK[(nt * 8 + r4) * KPAD + kk * 8 + c4 + 4]);
                mma_tf32(e[nt], qa[kk], b0, b1);
            }
        }

        int kb = kt * 64;
        #pragma unroll
        for (int nt = 0; nt < 8; nt++) {
            float2 mm0 = *(const float2*)&mrow0[kb + nt * 8 + 2 * c4];
            float2 mm1 = *(const float2*)&mrow1[kb + nt * 8 + 2 * c4];
            e[nt][0] *= mm0.x * SCALE;
            e[nt][1] *= mm0.y * SCALE;
            e[nt][2] *= mm1.x * SCALE;
            e[nt][3] *= mm1.y * SCALE;
        }

        float rm0 = -1e30f, rm1 = -1e30f;
        #pragma unroll
        for (int nt = 0; nt < 8; nt++) {
            rm0 = fmaxf(rm0, fmaxf(e[nt][0], e[nt][1]));
            rm1 = fmaxf(rm1, fmaxf(e[nt][2], e[nt][3]));
        }
        rm0 = fmaxf(rm0, __shfl_xor_sync(0xffffffffu, rm0, 1));
        rm0 = fmaxf(rm0, __shfl_xor_sync(0xffffffffu, rm0, 2));
        rm1 = fmaxf(rm1, __shfl_xor_sync(0xffffffffu, rm1, 1));
        rm1 = fmaxf(rm1, __shfl_xor_sync(0xffffffffu, rm1, 2));
        float mn0 = fmaxf(m0, rm0), mn1 = fmaxf(m1, rm1);
        float a0 = __expf(m0 - mn0), a1 = __expf(m1 - mn1);
        float rs0 = 0.f, rs1 = 0.f;
        #pragma unroll
        for (int nt = 0; nt < 8; nt++) {
            e[nt][0] = __expf(e[nt][0] - mn0);
            e[nt][1] = __expf(e[nt][1] - mn0);
            e[nt][2] = __expf(e[nt][2] - mn1);
            e[nt][3] = __expf(e[nt][3] - mn1);
            rs0 += e[nt][0] + e[nt][1];
            rs1 += e[nt][2] + e[nt][3];
        }
        rs0 += __shfl_xor_sync(0xffffffffu, rs0, 1);
        rs0 += __shfl_xor_sync(0xffffffffu, rs0, 2);
        rs1 += __shfl_xor_sync(0xffffffffu, rs1, 1);
        rs1 += __shfl_xor_sync(0xffffffffu, rs1, 2);
        l0 = l0 * a0 + rs0;
        l1 = l1 * a1 + rs1;
        m0 = mn0; m1 = mn1;

        #pragma unroll
        for (int nt = 0; nt < 8; nt++) {
            float2 p0, p1;
            p0.x = __uint_as_float(f2tf(e[nt][0]));
            p0.y = __uint_as_float(f2tf(e[nt][1]));
            p1.x = __uint_as_float(f2tf(e[nt][2]));
            p1.y = __uint_as_float(f2tf(e[nt][3]));
            *(float2*)&sPw[r4 * PPAD + nt * 8 + 2 * c4] = p0;
            *(float2*)&sPw[(r4 + 8) * PPAD + nt * 8 + 2 * c4] = p1;
            o[nt][0] *= a0; o[nt][1] *= a0;
            o[nt][2] *= a1; o[nt][3] *= a1;
        }
        __syncwarp();

        #pragma unroll
        for (int kk = 0; kk < 8; kk++) {
            unsigned pa[4];
            pa[0] = __float_as_uint(sPw[r4 * PPAD + kk * 8 + c4]);
            pa[1] = __float_as_uint(sPw[(r4 + 8) * PPAD + kk * 8 + c4]);
            pa[2] = __float_as_uint(sPw[r4 * PPAD + kk * 8 + c4 + 4]);
            pa[3] = __float_as_uint(sPw[(r4 + 8) * PPAD + kk * 8 + c4 + 4]);
            #pragma unroll
            for (int nt = 0; nt < 8; nt++) {
                unsigned b0 = __float_as_uint(sV[(kk * 8 + c4) * VPAD + nt * 8 + r4]);
                unsigned b1 = __float_as_uint(sV[(kk * 8 + c4 + 4) * VPAD + nt * 8 + r4]);
                mma_tf32(o[nt], pa, b0, b1);
            }
        }
        __syncwarp();
    }

    float inv0 = 1.f / l0, inv1 = 1.f / l1;
    size_t ob0 = ((size_t)(b * S + qw + r4)) * D + h * 64;
    size_t ob1 = ((size_t)(b * S + qw + r4 + 8)) * D + h * 64;
    #pragma unroll
    for (int nt = 0; nt < 8; nt++) {
        float2 v0, v1;
        v0.x = o[nt][0] * inv0; v0.y = o[nt][1] * inv0;
        v1.x = o[nt][2] * inv1; v1.y = o[nt][3] * inv1;
        *(float2*)&g_att[ob0 + nt * 8 + 2 * c4] = v0;
        *(float2*)&g_att[ob1 + nt * 8 + 2 * c4] = v1;
    }
}

// ---------------- kernel 6: out = att @ Wo^T + bo via tf32 mma ----------------
// Block tile 128(M) x 64(N), BK=64. 8 warps x 16 rows. Grid (64, 8).
__global__ void __launch_bounds__(256, 2) k_proj(const float* __restrict__ Wo,
                                                 const float* __restrict__ bo,
                                                 float* __restrict__ out) {
    extern __shared__ float sm[];
    float* sA = sm;               // 128 x 68
    float* sB = sm + 128 * GP;    // 64 x 68
    int tid = threadIdx.x;
    int w = tid >> 5, lane = tid & 31;
    int r4 = lane >> 2, c4 = lane & 3;
    int m0 = blockIdx.x * 128;
    int n0 = blockIdx.y * 64;

    float acc[8][4];
    #pragma unroll
    for (int nt = 0; nt < 8; nt++)
        #pragma unroll
        for (int j = 0; j < 4; j++) acc[nt][j] = 0.f;

    for (int k0 = 0; k0 < D; k0 += 64) {
        __syncthreads();
        // stage A 128x64
        #pragma unroll
        for (int t = 0; t < 8; t++) {
            int idx = (tid + t * 256) * 4;
            int r = idx >> 6, c = idx & 63;
            float4 v = *(const float4*)&g_att[(size_t)(m0 + r) * D + k0 + c];
            uint4 uu = make_uint4(f2tf(v.x), f2tf(v.y), f2tf(v.z), f2tf(v.w));
            *(uint4*)&sA[r * GP + c] = uu;
        }
        // stage B 64x64 (Wo rows n0..n0+63, cols k0..k0+63)
        #pragma unroll
        for (int t = 0; t < 4; t++) {
            int idx = (tid + t * 256) * 4;
            int r = idx >> 6, c = idx & 63;
            float4 v = *(const float4*)&Wo[(size_t)(n0 + r) * D + k0 + c];
            uint4 uu = make_uint4(f2tf(v.x), f2tf(v.y), f2tf(v.z), f2tf(v.w));
            *(uint4*)&sB[r * GP + c] = uu;
        }
        __syncthreads();

        const float* Aw = sA + (w * 16) * GP;
        unsigned af[8][4];
        #pragma unroll
        for (int kk = 0; kk < 8; kk++) {
            af[kk][0] = __float_as_uint(Aw[r4 * GP + kk * 8 + c4]);
            af[kk][1] = __float_as_uint(Aw[(r4 + 8) * GP + kk * 8 + c4]);
            af[kk][2] = __float_as_uint(Aw[r4 * GP + kk * 8 + c4 + 4]);
            af[kk][3] = __float_as_uint(Aw[(r4 + 8) * GP + kk * 8 + c4 + 4]);
        }
        #pragma unroll
        for (int nt = 0; nt < 8; nt++) {
            #pragma unroll
            for (int kk = 0; kk < 8; kk++) {
                unsigned b0 = __float_as_uint(sB[(nt * 8 + r4) * GP + kk * 8 + c4]);
                unsigned b1 = __float_as_uint(sB[(nt * 8 + r4) * GP + kk * 8 + c4 + 4]);
                mma_tf32(acc[nt], af[kk], b0, b1);
            }
        }
    }

    int row0 = m0 + w * 16 + r4;
    #pragma unroll
    for (int nt = 0; nt < 8; nt++) {
        int n = n0 + nt * 8 + 2 * c4;
        float2 bb = *(const float2*)&bo[n];
        float2 v0, v1;
        v0.x = acc[nt][0] + bb.x; v0.y = acc[nt][1] + bb.y;
        v1.x = acc[nt][2] + bb.x; v1.y = acc[nt][3] + bb.y;
        *(float2*)&out[(size_t)row0 * D + n] = v0;
        *(float2*)&out[(size_t)(row0 + 8) * D + n] = v1;
    }
}

// ---------------- launch ----------------
extern "C" void kernel_launch(void* const* d_in, const int* in_sizes, int n_in,
                              void* d_out, int out_size) {
    const int*   x   = (const int*)d_in[0];
    const float* emb = (const float*)d_in[1];
    const float* Wq  = (const float*)d_in[2];
    const float* Wk  = (const float*)d_in[3];
    const float* Wv  = (const float*)d_in[4];
    const float* Wo  = (const float*)d_in[5];
    const float* bo  = (const float*)d_in[6];
    const float* Wc  = (const float*)d_in[7];
    const float* bc  = (const float*)d_in[8];
    float* out = (float*)d_out;
    float* maskout = out + (size_t)B * S * D;

    k_embed<<<BS, 256>>>(x, emb, Wc, bc);
    k_norm<<<B, S>>>();
    dim3 mg(S, B);
    k_mask<<<mg, 256>>>(maskout);

    size_t qkv_smem = (128 * GP + 3 * 64 * GP) * sizeof(float);   // 87040 B
    cudaFuncSetAttribute(k_qkv, cudaFuncAttributeMaxDynamicSharedMemorySize, (int)qkv_smem);
    dim3 qg(BS / 128, H);
    k_qkv<<<qg, 256, qkv_smem>>>(Wq, Wk, Wv);

    size_t attn_smem = (64 * KPAD + 64 * VPAD + 128 * PPAD) * sizeof(float);  // 70656 B
    cudaFuncSetAttribute(k_attn, cudaFuncAttributeMaxDynamicSharedMemorySize, (int)attn_smem);
    k_attn<<<B * H * (S / 128), 256, attn_smem>>>(maskout);

    size_t proj_smem = (128 * GP + 64 * GP) * sizeof(float);      // 52224 B
    cudaFuncSetAttribute(k_proj, cudaFuncAttributeMaxDynamicSharedMemorySize, (int)proj_smem);
    dim3 pg(BS / 128, D / 64);
    k_proj<<<pg, 256, proj_smem>>>(Wo, bo, out);
}

// round 5
// speedup vs baseline: 5.2767x; 1.0435x over previous
#include <cuda_runtime.h>
#include <math.h>

#define B 8
#define S 1024
#define D 512
#define H 8
#define HD 64
#define BS (B*S)
#define SCALE 0.044194173824159216f  // 1/sqrt(512)

// ---------------- scratch (static device globals; no allocation) ----------------
__device__ float g_h[BS * D];
__device__ float g_pe[S * D];          // positional encoding table
__device__ float g_w[BS];
__device__ float g_q[B * H * S * HD];  // [b,h,s,d]
__device__ float g_k[B * H * S * HD];
__device__ float g_v[B * H * S * HD];
__device__ float g_att[BS * D];

// ---------------- helpers ----------------
__device__ __forceinline__ unsigned f2tf(float f) {
    unsigned u;
    asm("cvt.rna.tf32.f32 %0, %1;" : "=r"(u) : "f"(f));
    return u;
}
__device__ __forceinline__ void mma_tf32(float d[4], const unsigned a[4],
                                         unsigned b0, unsigned b1) {
    asm("mma.sync.aligned.m16n8k8.row.col.f32.tf32.tf32.f32 "
        "{%0,%1,%2,%3}, {%4,%5,%6,%7}, {%8,%9}, {%0,%1,%2,%3};"
        : "+f"(d[0]), "+f"(d[1]), "+f"(d[2]), "+f"(d[3])
        : "r"(a[0]), "r"(a[1]), "r"(a[2]), "r"(a[3]), "r"(b0), "r"(b1));
}

// ---------------- kernel 0: PE table (depends only on s,d) ----------------
__global__ void k_pe() {
    int s = blockIdx.x;
    const float c = -logf(10000.0f) / (float)D;
    #pragma unroll
    for (int t = 0; t < 2; t++) {
        int d = threadIdx.x + t * 256;
        int i2 = d & ~1;
        float ang = (float)s * expf(c * (float)i2);
        g_pe[s * D + d] = (d & 1) ? cosf(ang) : sinf(ang);
    }
}

// ---------------- kernel 1: h = emb[x] + PE, width_raw = h . Wc + bc ----------------
// one block (128 thr) per row, float4 throughout
__global__ void __launch_bounds__(128) k_embed(const int* __restrict__ x,
                                               const float* __restrict__ emb,
                                               const float* __restrict__ Wc,
                                               const float* __restrict__ bc) {
    int bs = blockIdx.x;
    int s = bs & (S - 1);
    int tok = x[bs];
    int t = threadIdx.x;
    const float4* e4 = (const float4*)(emb + (size_t)tok * D);
    const float4* p4 = (const float4*)(g_pe + (size_t)s * D);
    const float4* w4 = (const float4*)Wc;
    float4* h4 = (float4*)(g_h + (size_t)bs * D);

    float4 e = e4[t], p = p4[t], w = w4[t];
    float4 hv;
    hv.x = e.x + p.x; hv.y = e.y + p.y; hv.z = e.z + p.z; hv.w = e.w + p.w;
    h4[t] = hv;
    float wsum = hv.x * w.x + hv.y * w.y + hv.z * w.z + hv.w * w.w;

    #pragma unroll
    for (int off = 16; off; off >>= 1)
        wsum += __shfl_xor_sync(0xffffffffu, wsum, off);
    __shared__ float red[4];
    if ((t & 31) == 0) red[t >> 5] = wsum;
    __syncthreads();
    if (t == 0)
        g_w[bs] = red[0] + red[1] + red[2] + red[3] + bc[0];
}

// ---------------- kernel 2: per-batch min-max normalize ----------------
__global__ void k_norm() {
    int b = blockIdx.x;
    int t = threadIdx.x;
    float v = g_w[b * S + t];
    float mn = v, mx = v;
    __shared__ float smin[32], smax[32];
    #pragma unroll
    for (int off = 16; off; off >>= 1) {
        mn = fminf(mn, __shfl_xor_sync(0xffffffffu, mn, off));
        mx = fmaxf(mx, __shfl_xor_sync(0xffffffffu, mx, off));
    }
    if ((t & 31) == 0) { smin[t >> 5] = mn; smax[t >> 5] = mx; }
    __syncthreads();
    if (t < 32) {
        mn = smin[t]; mx = smax[t];
        #pragma unroll
        for (int off = 16; off; off >>= 1) {
            mn = fminf(mn, __shfl_xor_sync(0xffffffffu, mn, off));
            mx = fmaxf(mx, __shfl_xor_sync(0xffffffffu, mx, off));
        }
        if (t == 0) { smin[0] = mn; smax[0] = mx; }
    }
    __syncthreads();
    float lo = smin[0], hi = smax[0];
    g_w[b * S + t] = (v - lo) / (hi - lo);
}

// ---------------- kernel 3: mask (fast __expf, float4 stores) ----------------
__global__ void __launch_bounds__(256) k_mask(float* __restrict__ mout) {
    int i = blockIdx.x, b = blockIdx.y;
    float w = g_w[b * S + i];
    float4* mrow4 = (float4*)(mout + ((size_t)b * S + i) * S);
    bool lower = (i < S / 2);
    int j0 = threadIdx.x * 4;
    float r[4];
    #pragma unroll
    for (int u = 0; u < 4; u++) {
        int j = j0 + u;
        int idx = (S / 2 - 1 - i + j) & (S - 1);
        float origin = (idx < S / 2) ? (1.0f - (float)idx * (1.0f / (float)(S / 2 - 1)))
                                     : ((float)(idx - S / 2) * (1.0f / (float)(S / 2 - 1)));
        bool cmp = (idx >= j);
        bool move = lower ? cmp : !cmp;
        float val = 0.f;
        if (move) {
            float z = (origin - w) * 100.f;
            val = 1.f / (1.f + __expf(z));
        }
        r[u] = val;
    }
    mrow4[threadIdx.x] = make_float4(r[0], r[1], r[2], r[3]);
}

// ---------------- kernel 4: QKV via tf32 mma ----------------
#define GP 68
__global__ void __launch_bounds__(256) k_qkv(const float* __restrict__ Wq,
                                             const float* __restrict__ Wk,
                                             const float* __restrict__ Wv) {
    extern __shared__ float sm[];
    float* sA = sm;               // 128 x 68
    float* sB = sm + 128 * GP;    // 3 x 64 x 68
    int tid = threadIdx.x;
    int w = tid >> 5, lane = tid & 31;
    int r4 = lane >> 2, c4 = lane & 3;
    int m0 = blockIdx.x * 128;
    int h = blockIdx.y;

    #pragma unroll
    for (int t = 0; t < 8; t++) {
        int idx = (tid + t * 256) * 4;
        int r = idx >> 6, c = idx & 63;
        float4 v = *(const float4*)&g_h[(size_t)(m0 + r) * D + h * 64 + c];
        uint4 uu = make_uint4(f2tf(v.x), f2tf(v.y), f2tf(v.z), f2tf(v.w));
        *(uint4*)&sA[r * GP + c] = uu;
    }
    const float* Ws[3] = {Wq, Wk, Wv};
    #pragma unroll
    for (int wi = 0; wi < 3; wi++) {
        #pragma unroll
        for (int t = 0; t < 4; t++) {
            int idx = (tid + t * 256) * 4;
            int r = idx >> 6, c = idx & 63;
            float4 v = *(const float4*)&Ws[wi][(size_t)r * 64 + c];
            uint4 uu = make_uint4(f2tf(v.x), f2tf(v.y), f2tf(v.z), f2tf(v.w));
            *(uint4*)&sB[(wi * 64 + r) * GP + c] = uu;
        }
    }
    __syncthreads();

    const float* Aw = sA + (w * 16) * GP;
    unsigned af[8][4];
    #pragma unroll
    for (int kk = 0; kk < 8; kk++) {
        af[kk][0] = __float_as_uint(Aw[r4 * GP + kk * 8 + c4]);
        af[kk][1] = __float_as_uint(Aw[(r4 + 8) * GP + kk * 8 + c4]);
        af[kk][2] = __float_as_uint(Aw[r4 * GP + kk * 8 + c4 + 4]);
        af[kk][3] = __float_as_uint(Aw[(r4 + 8) * GP + kk * 8 + c4 + 4]);
    }

    int row0 = m0 + w * 16 + r4;
    float* outs[3] = {g_q, g_k, g_v};
    #pragma unroll
    for (int wi = 0; wi < 3; wi++) {
        float acc[8][4];
        #pragma unroll
        for (int nt = 0; nt < 8; nt++) {
            #pragma unroll
            for (int j = 0; j < 4; j++) acc[nt][j] = 0.f;
            #pragma unroll
            for (int kk = 0; kk < 8; kk++) {
                unsigned b0 = __float_as_uint(sB[(wi * 64 + nt * 8 + r4) * GP + kk * 8 + c4]);
                unsigned b1 = __float_as_uint(sB[(wi * 64 + nt * 8 + r4) * GP + kk * 8 + c4 + 4]);
                mma_tf32(acc[nt], af[kk], b0, b1);
            }
        }
        int b0r = row0 >> 10, s0 = row0 & (S - 1);
        int b1r = (row0 + 8) >> 10, s1 = (row0 + 8) & (S - 1);
        size_t q0 = (((size_t)b0r * H + h) * S + s0) * HD;
        size_t q1 = (((size_t)b1r * H + h) * S + s1) * HD;
        float* op = outs[wi];
        #pragma unroll
        for (int nt = 0; nt < 8; nt++) {
            float2 v0, v1;
            v0.x = acc[nt][0]; v0.y = acc[nt][1];
            v1.x = acc[nt][2]; v1.y = acc[nt][3];
            *(float2*)&op[q0 + nt * 8 + 2 * c4] = v0;
            *(float2*)&op[q1 + nt * 8 + 2 * c4] = v1;
        }
    }
}

// ---------------- kernel 5: tensor-core (tf32 mma.sync) flash attention ----------------
#define KPAD 68
#define VPAD 72
#define PPAD 68
__global__ void __launch_bounds__(256, 2) k_attn(const float* __restrict__ mask) {
    extern __shared__ float smx[];
    float* sK = smx;                     // 64*68
    float* sV = sK + 64 * KPAD;          // 64*72
    float* sP = sV + 64 * VPAD;          // 128*68

    int tid = threadIdx.x;
    int w = tid >> 5, lane = tid & 31;
    int r4 = lane >> 2, c4 = lane & 3;
    int qt = blockIdx.x & 7;
    int bh = blockIdx.x >> 3;
    int h = bh & 7, b = bh >> 3;
    size_t base = (size_t)bh * S * HD;
    int qw = qt * 128 + w * 16;

    unsigned qa[8][4];
    {
        const float* qb = g_q + base + (size_t)qw * HD;
        #pragma unroll
        for (int kk = 0; kk < 8; kk++) {
            qa[kk][0] = f2tf(qb[(size_t)r4 * 64 + kk * 8 + c4]);
            qa[kk][1] = f2tf(qb[(size_t)(r4 + 8) * 64 + kk * 8 + c4]);
            qa[kk][2] = f2tf(qb[(size_t)r4 * 64 + kk * 8 + c4 + 4]);
            qa[kk][3] = f2tf(qb[(size_t)(r4 + 8) * 64 + kk * 8 + c4 + 4]);
        }
    }

    float o[8][4];
    #pragma unroll
    for (int nt = 0; nt < 8; nt++)
        #pragma unroll
        for (int j = 0; j < 4; j++) o[nt][j] = 0.f;
    float m0 = -1e30f, m1 = -1e30f, l0 = 0.f, l1 = 0.f;

    const float* mrow0 = mask + ((size_t)h * S + qw + r4) * S;
    const float* mrow1 = mrow0 + (size_t)8 * S;
    float* sPw = sP + w * 16 * PPAD;

    for (int kt = 0; kt < S / 64; kt++) {
        __syncthreads();
        const float* gk = g_k + base + (size_t)kt * 64 * 64;
        const float* gv = g_v + base + (size_t)kt * 64 * 64;
        #pragma unroll 4
        for (int i = tid; i < 64 * 64; i += 256) {
            int key = i >> 6, d = i & 63;
            sK[key * KPAD + d] = __uint_as_float(f2tf(gk[i]));
            sV[key * VPAD + d] = __uint_as_float(f2tf(gv[i]));
        }
        __syncthreads();

        float e[8][4];
        #pragma unroll
        for (int nt = 0; nt < 8; nt++) {
            #pragma unroll
            for (int j = 0; j < 4; j++) e[nt][j] = 0.f;
            #pragma unroll
            for (int kk = 0; kk < 8; kk++) {
                unsigned b0 = __float_as_uint(sK[(nt * 8 + r4) * KPAD + kk * 8 + c4]);
                unsigned b1 = __float_as_uint(sK[(nt * 8 + r4) * KPAD + kk * 8 + c4 + 4]);
                mma_tf32(e[nt], qa[kk], b0, b1);
            }
        }

        int kb = kt * 64;
        #pragma unroll
        for (int nt = 0; nt < 8; nt++) {
            float2 mm0 = *(const float2*)&mrow0[kb + nt * 8 + 2 * c4];
            float2 mm1 = *(const float2*)&mrow1[kb + nt * 8 + 2 * c4];
            e[nt][0] *= mm0.x * SCALE;
            e[nt][1] *= mm0.y * SCALE;
            e[nt][2] *= mm1.x * SCALE;
            e[nt][3] *= mm1.y * SCALE;
        }

        float rm0 = -1e30f, rm1 = -1e30f;
        #pragma unroll
        for (int nt = 0; nt < 8; nt++) {
            rm0 = fmaxf(rm0, fmaxf(e[nt][0], e[nt][1]));
            rm1 = fmaxf(rm1, fmaxf(e[nt][2], e[nt][3]));
        }
        rm0 = fmaxf(rm0, __shfl_xor_sync(0xffffffffu, rm0, 1));
        rm0 = fmaxf(rm0, __shfl_xor_sync(0xffffffffu, rm0, 2));
        rm1 = fmaxf(rm1, __shfl_xor_sync(0xffffffffu, rm1, 1));
        rm1 = fmaxf(rm1, __shfl_xor_sync(0xffffffffu, rm1, 2));
        float mn0 = fmaxf(m0, rm0), mn1 = fmaxf(m1, rm1);
        float a0 = __expf(m0 - mn0), a1 = __expf(m1 - mn1);
        float rs0 = 0.f, rs1 = 0.f;
        #pragma unroll
        for (int nt = 0; nt < 8; nt++) {
            e[nt][0] = __expf(e[nt][0] - mn0);
            e[nt][1] = __expf(e[nt][1] - mn0);
            e[nt][2] = __expf(e[nt][2] - mn1);
            e[nt][3] = __expf(e[nt][3] - mn1);
            rs0 += e[nt][0] + e[nt][1];
            rs1 += e[nt][2] + e[nt][3];
        }
        rs0 += __shfl_xor_sync(0xffffffffu, rs0, 1);
        rs0 += __shfl_xor_sync(0xffffffffu, rs0, 2);
        rs1 += __shfl_xor_sync(0xffffffffu, rs1, 1);
        rs1 += __shfl_xor_sync(0xffffffffu, rs1, 2);
        l0 = l0 * a0 + rs0;
        l1 = l1 * a1 + rs1;
        m0 = mn0; m1 = mn1;

        #pragma unroll
        for (int nt = 0; nt < 8; nt++) {
            float2 p0, p1;
            p0.x = __uint_as_float(f2tf(e[nt][0]));
            p0.y = __uint_as_float(f2tf(e[nt][1]));
            p1.x = __uint_as_float(f2tf(e[nt][2]));
            p1.y = __uint_as_float(f2tf(e[nt][3]));
            *(float2*)&sPw[r4 * PPAD + nt * 8 + 2 * c4] = p0;
            *(float2*)&sPw[(r4 + 8) * PPAD + nt * 8 + 2 * c4] = p1;
            o[nt][0] *= a0; o[nt][1] *= a0;
            o[nt][2] *= a1; o[nt][3] *= a1;
        }
        __syncwarp();

        #pragma unroll
        for (int kk = 0; kk < 8; kk++) {
            unsigned pa[4];
            pa[0] = __float_as_uint(sPw[r4 * PPAD + kk * 8 + c4]);
            pa[1] = __float_as_uint(sPw[(r4 + 8) * PPAD + kk * 8 + c4]);
            pa[2] = __float_as_uint(sPw[r4 * PPAD + kk * 8 + c4 + 4]);
            pa[3] = __float_as_uint(sPw[(r4 + 8) * PPAD + kk * 8 + c4 + 4]);
            #pragma unroll
            for (int nt = 0; nt < 8; nt++) {
                unsigned b0 = __float_as_uint(sV[(kk * 8 + c4) * VPAD + nt * 8 + r4]);
                unsigned b1 = __float_as_uint(sV[(kk * 8 + c4 + 4) * VPAD + nt * 8 + r4]);
                mma_tf32(o[nt], pa, b0, b1);
            }
        }
        __syncwarp();
    }

    float inv0 = 1.f / l0, inv1 = 1.f / l1;
    size_t ob0 = ((size_t)(b * S + qw + r4)) * D + h * 64;
    size_t ob1 = ((size_t)(b * S + qw + r4 + 8)) * D + h * 64;
    #pragma unroll
    for (int nt = 0; nt < 8; nt++) {
        float2 v0, v1;
        v0.x = o[nt][0] * inv0; v0.y = o[nt][1] * inv0;
        v1.x = o[nt][2] * inv1; v1.y = o[nt][3] * inv1;
        *(float2*)&g_att[ob0 + nt * 8 + 2 * c4] = v0;
        *(float2*)&g_att[ob1 + nt * 8 + 2 * c4] = v1;
    }
}

// ---------------- kernel 6: out = att @ Wo^T + bo via tf32 mma ----------------
__global__ void __launch_bounds__(256, 2) k_proj(const float* __restrict__ Wo,
                                                 const float* __restrict__ bo,
                                                 float* __restrict__ out) {
    extern __shared__ float sm[];
    float* sA = sm;               // 128 x 68
    float* sB = sm + 128 * GP;    // 64 x 68
    int tid = threadIdx.x;
    int w = tid >> 5, lane = tid & 31;
    int r4 = lane >> 2, c4 = lane & 3;
    int m0 = blockIdx.x * 128;
    int n0 = blockIdx.y * 64;

    float acc[8][4];
    #pragma unroll
    for (int nt = 0; nt < 8; nt++)
        #pragma unroll
        for (int j = 0; j < 4; j++) acc[nt][j] = 0.f;

    for (int k0 = 0; k0 < D; k0 += 64) {
        __syncthreads();
        #pragma unroll
        for (int t = 0; t < 8; t++) {
            int idx = (tid + t * 256) * 4;
            int r = idx >> 6, c = idx & 63;
            float4 v = *(const float4*)&g_att[(size_t)(m0 + r) * D + k0 + c];
            uint4 uu = make_uint4(f2tf(v.x), f2tf(v.y), f2tf(v.z), f2tf(v.w));
            *(uint4*)&sA[r * GP + c] = uu;
        }
        #pragma unroll
        for (int t = 0; t < 4; t++) {
            int idx = (tid + t * 256) * 4;
            int r = idx >> 6, c = idx & 63;
            float4 v = *(const float4*)&Wo[(size_t)(n0 + r) * D + k0 + c];
            uint4 uu = make_uint4(f2tf(v.x), f2tf(v.y), f2tf(v.z), f2tf(v.w));
            *(uint4*)&sB[r * GP + c] = uu;
        }
        __syncthreads();

        const float* Aw = sA + (w * 16) * GP;
        unsigned af[8][4];
        #pragma unroll
        for (int kk = 0; kk < 8; kk++) {
            af[kk][0] = __float_as_uint(Aw[r4 * GP + kk * 8 + c4]);
            af[kk][1] = __float_as_uint(Aw[(r4 + 8) * GP + kk * 8 + c4]);
            af[kk][2] = __float_as_uint(Aw[r4 * GP + kk * 8 + c4 + 4]);
            af[kk][3] = __float_as_uint(Aw[(r4 + 8) * GP + kk * 8 + c4 + 4]);
        }
        #pragma unroll
        for (int nt = 0; nt < 8; nt++) {
            #pragma unroll
            for (int kk = 0; kk < 8; kk++) {
                unsigned b0 = __float_as_uint(sB[(nt * 8 + r4) * GP + kk * 8 + c4]);
                unsigned b1 = __float_as_uint(sB[(nt * 8 + r4) * GP + kk * 8 + c4 + 4]);
                mma_tf32(acc[nt], af[kk], b0, b1);
            }
        }
    }

    int row0 = m0 + w * 16 + r4;
    #pragma unroll
    for (int nt = 0; nt < 8; nt++) {
        int n = n0 + nt * 8 + 2 * c4;
        float2 bb = *(const float2*)&bo[n];
        float2 v0, v1;
        v0.x = acc[nt][0] + bb.x; v0.y = acc[nt][1] + bb.y;
        v1.x = acc[nt][2] + bb.x; v1.y = acc[nt][3] + bb.y;
        *(float2*)&out[(size_t)row0 * D + n] = v0;
        *(float2*)&out[(size_t)(row0 + 8) * D + n] = v1;
    }
}

// ---------------- launch ----------------
extern "C" void kernel_launch(void* const* d_in, const int* in_sizes, int n_in,
                              void* d_out, int out_size) {
    const int*   x   = (const int*)d_in[0];
    const float* emb = (const float*)d_in[1];
    const float* Wq  = (const float*)d_in[2];
    const float* Wk  = (const float*)d_in[3];
    const float* Wv  = (const float*)d_in[4];
    const float* Wo  = (const float*)d_in[5];
    const float* bo  = (const float*)d_in[6];
    const float* Wc  = (const float*)d_in[7];
    const float* bc  = (const float*)d_in[8];
    float* out = (float*)d_out;
    float* maskout = out + (size_t)B * S * D;

    k_pe<<<S, 256>>>();
    k_embed<<<BS, 128>>>(x, emb, Wc, bc);
    k_norm<<<B, S>>>();
    dim3 mg(S, B);
    k_mask<<<mg, 256>>>(maskout);

    size_t qkv_smem = (128 * GP + 3 * 64 * GP) * sizeof(float);
    cudaFuncSetAttribute(k_qkv, cudaFuncAttributeMaxDynamicSharedMemorySize, (int)qkv_smem);
    dim3 qg(BS / 128, H);
    k_qkv<<<qg, 256, qkv_smem>>>(Wq, Wk, Wv);

    size_t attn_smem = (64 * KPAD + 64 * VPAD + 128 * PPAD) * sizeof(float);
    cudaFuncSetAttribute(k_attn, cudaFuncAttributeMaxDynamicSharedMemorySize, (int)attn_smem);
    k_attn<<<B * H * (S / 128), 256, attn_smem>>>(maskout);

    size_t proj_smem = (128 * GP + 64 * GP) * sizeof(float);
    cudaFuncSetAttribute(k_proj, cudaFuncAttributeMaxDynamicSharedMemorySize, (int)proj_smem);
    dim3 pg(BS / 128, D / 64);
    k_proj<<<pg, 256, proj_smem>>>(Wo, bo, out);
}

// round 6
// speedup vs baseline: 7.2090x; 1.3662x over previous
#include <cuda_runtime.h>
#include <cuda_fp16.h>
#include <math.h>

#define B 8
#define S 1024
#define D 512
#define H 8
#define HD 64
#define BS (B*S)
#define SCALE 0.044194173824159216f  // 1/sqrt(512)
#define HP 72   // half-element row pad: banks (4*r4+c4)%32 conflict-free

// ---------------- scratch (static device globals; no allocation) ----------------
__device__ float  g_pe[S * D];
__device__ float  g_w[BS];
__device__ __half g_hh[BS * D];          // fp16 h for GEMMs
__device__ __half g_q[B * H * S * HD];   // [b,h,s,d]
__device__ __half g_k[B * H * S * HD];
__device__ __half g_v[B * H * S * HD];
__device__ __half g_att[BS * D];

// ---------------- helpers ----------------
__device__ __forceinline__ void mma_f16(float d[4], const unsigned a[4],
                                        unsigned b0, unsigned b1) {
    asm("mma.sync.aligned.m16n8k16.row.col.f32.f16.f16.f32 "
        "{%0,%1,%2,%3}, {%4,%5,%6,%7}, {%8,%9}, {%0,%1,%2,%3};"
        : "+f"(d[0]), "+f"(d[1]), "+f"(d[2]), "+f"(d[3])
        : "r"(a[0]), "r"(a[1]), "r"(a[2]), "r"(a[3]), "r"(b0), "r"(b1));
}

// ---------------- kernel 0: PE table ----------------
__global__ void k_pe() {
    int s = blockIdx.x;
    const float c = -logf(10000.0f) / (float)D;
    #pragma unroll
    for (int t = 0; t < 2; t++) {
        int d = threadIdx.x + t * 256;
        int i2 = d & ~1;
        float ang = (float)s * expf(c * (float)i2);
        g_pe[s * D + d] = (d & 1) ? cosf(ang) : sinf(ang);
    }
}

// ---------------- kernel 1: h = emb[x]+PE (fp32 math, fp16 store), width dot fp32 ----------------
__global__ void __launch_bounds__(128) k_embed(const int* __restrict__ x,
                                               const float* __restrict__ emb,
                                               const float* __restrict__ Wc,
                                               const float* __restrict__ bc) {
    int bs = blockIdx.x;
    int s = bs & (S - 1);
    int tok = x[bs];
    int t = threadIdx.x;
    const float4* e4 = (const float4*)(emb + (size_t)tok * D);
    const float4* p4 = (const float4*)(g_pe + (size_t)s * D);
    const float4* w4 = (const float4*)Wc;

    float4 e = e4[t], p = p4[t], w = w4[t];
    float4 hv;
    hv.x = e.x + p.x; hv.y = e.y + p.y; hv.z = e.z + p.z; hv.w = e.w + p.w;
    __half2* hh = (__half2*)(g_hh + (size_t)bs * D + t * 4);
    hh[0] = __floats2half2_rn(hv.x, hv.y);
    hh[1] = __floats2half2_rn(hv.z, hv.w);
    float wsum = hv.x * w.x + hv.y * w.y + hv.z * w.z + hv.w * w.w;

    #pragma unroll
    for (int off = 16; off; off >>= 1)
        wsum += __shfl_xor_sync(0xffffffffu, wsum, off);
    __shared__ float red[4];
    if ((t & 31) == 0) red[t >> 5] = wsum;
    __syncthreads();
    if (t == 0)
        g_w[bs] = red[0] + red[1] + red[2] + red[3] + bc[0];
}

// ---------------- kernel 2: per-batch min-max normalize ----------------
__global__ void k_norm() {
    int b = blockIdx.x;
    int t = threadIdx.x;
    float v = g_w[b * S + t];
    float mn = v, mx = v;
    __shared__ float smin[32], smax[32];
    #pragma unroll
    for (int off = 16; off; off >>= 1) {
        mn = fminf(mn, __shfl_xor_sync(0xffffffffu, mn, off));
        mx = fmaxf(mx, __shfl_xor_sync(0xffffffffu, mx, off));
    }
    if ((t & 31) == 0) { smin[t >> 5] = mn; smax[t >> 5] = mx; }
    __syncthreads();
    if (t < 32) {
        mn = smin[t]; mx = smax[t];
        #pragma unroll
        for (int off = 16; off; off >>= 1) {
            mn = fminf(mn, __shfl_xor_sync(0xffffffffu, mn, off));
            mx = fmaxf(mx, __shfl_xor_sync(0xffffffffu, mx, off));
        }
        if (t == 0) { smin[0] = mn; smax[0] = mx; }
    }
    __syncthreads();
    float lo = smin[0], hi = smax[0];
    g_w[b * S + t] = (v - lo) / (hi - lo);
}

// ---------------- kernel 3: mask ----------------
__global__ void __launch_bounds__(256) k_mask(float* __restrict__ mout) {
    int i = blockIdx.x, b = blockIdx.y;
    float w = g_w[b * S + i];
    float4* mrow4 = (float4*)(mout + ((size_t)b * S + i) * S);
    bool lower = (i < S / 2);
    int j0 = threadIdx.x * 4;
    float r[4];
    #pragma unroll
    for (int u = 0; u < 4; u++) {
        int j = j0 + u;
        int idx = (S / 2 - 1 - i + j) & (S - 1);
        float origin = (idx < S / 2) ? (1.0f - (float)idx * (1.0f / (float)(S / 2 - 1)))
                                     : ((float)(idx - S / 2) * (1.0f / (float)(S / 2 - 1)));
        bool cmp = (idx >= j);
        bool move = lower ? cmp : !cmp;
        float val = 0.f;
        if (move) {
            float z = (origin - w) * 100.f;
            val = 1.f / (1.f + __expf(z));
        }
        r[u] = val;
    }
    mrow4[threadIdx.x] = make_float4(r[0], r[1], r[2], r[3]);
}

// ---------------- kernel 4: QKV via fp16 mma ----------------
__global__ void __launch_bounds__(256) k_qkv(const float* __restrict__ Wq,
                                             const float* __restrict__ Wk,
                                             const float* __restrict__ Wv) {
    extern __shared__ __half smh[];
    __half* sA = smh;                 // 128 x 72
    __half* sB = smh + 128 * HP;      // 3 x 64 x 72
    int tid = threadIdx.x;
    int w = tid >> 5, lane = tid & 31;
    int r4 = lane >> 2, c4 = lane & 3;
    int m0 = blockIdx.x * 128;
    int h = blockIdx.y;

    // stage A: g_hh rows m0..m0+127, cols h*64..+63 (uint2 = 4 halves)
    #pragma unroll
    for (int t = 0; t < 8; t++) {
        int idx = tid + t * 256;              // 2048 quads
        int r = idx >> 4, c = (idx & 15) * 4;
        uint2 q = *(const uint2*)&g_hh[(size_t)(m0 + r) * D + h * 64 + c];
        *(uint2*)&sA[r * HP + c] = q;
    }
    // stage weights fp32 -> half
    const float* Ws[3] = {Wq, Wk, Wv};
    #pragma unroll
    for (int wi = 0; wi < 3; wi++) {
        #pragma unroll
        for (int t = 0; t < 4; t++) {
            int idx = tid + t * 256;          // 1024 quads
            int r = idx >> 4, c = (idx & 15) * 4;
            float4 v = *(const float4*)&Ws[wi][(size_t)r * 64 + c];
            __half2 h01 = __floats2half2_rn(v.x, v.y);
            __half2 h23 = __floats2half2_rn(v.z, v.w);
            *(__half2*)&sB[(wi * 64 + r) * HP + c] = h01;
            *(__half2*)&sB[(wi * 64 + r) * HP + c + 2] = h23;
        }
    }
    __syncthreads();

    // A fragments (4 K-steps of 16)
    const __half* Aw = sA + (w * 16) * HP;
    unsigned af[4][4];
    #pragma unroll
    for (int kk = 0; kk < 4; kk++) {
        af[kk][0] = *(const unsigned*)&Aw[r4 * HP + kk * 16 + 2 * c4];
        af[kk][1] = *(const unsigned*)&Aw[(r4 + 8) * HP + kk * 16 + 2 * c4];
        af[kk][2] = *(const unsigned*)&Aw[r4 * HP + kk * 16 + 2 * c4 + 8];
        af[kk][3] = *(const unsigned*)&Aw[(r4 + 8) * HP + kk * 16 + 2 * c4 + 8];
    }

    int row0 = m0 + w * 16 + r4;
    __half* outs[3] = {g_q, g_k, g_v};
    #pragma unroll
    for (int wi = 0; wi < 3; wi++) {
        float acc[8][4];
        #pragma unroll
        for (int nt = 0; nt < 8; nt++) {
            #pragma unroll
            for (int j = 0; j < 4; j++) acc[nt][j] = 0.f;
            #pragma unroll
            for (int kk = 0; kk < 4; kk++) {
                const __half* bp = &sB[(wi * 64 + nt * 8 + r4) * HP + kk * 16 + 2 * c4];
                unsigned b0 = *(const unsigned*)bp;
                unsigned b1 = *(const unsigned*)(bp + 8);
                mma_f16(acc[nt], af[kk], b0, b1);
            }
        }
        int b0r = row0 >> 10, s0 = row0 & (S - 1);
        int b1r = (row0 + 8) >> 10, s1 = (row0 + 8) & (S - 1);
        size_t q0 = (((size_t)b0r * H + h) * S + s0) * HD;
        size_t q1 = (((size_t)b1r * H + h) * S + s1) * HD;
        __half* op = outs[wi];
        #pragma unroll
        for (int nt = 0; nt < 8; nt++) {
            *(__half2*)&op[q0 + nt * 8 + 2 * c4] = __floats2half2_rn(acc[nt][0], acc[nt][1]);
            *(__half2*)&op[q1 + nt * 8 + 2 * c4] = __floats2half2_rn(acc[nt][2], acc[nt][3]);
        }
    }
}

// ---------------- kernel 5: fp16 mma flash attention ----------------
__global__ void __launch_bounds__(256, 2) k_attn(const float* __restrict__ mask) {
    extern __shared__ __half smh[];
    __half* sK  = smh;                    // [key][d] 64 x 72
    __half* sVT = smh + 64 * HP;          // [d][key] 64 x 72
    __half* sP  = sVT + 64 * HP;          // [q][key] 128 x 72 (per-warp 16-row slices)

    int tid = threadIdx.x;
    int w = tid >> 5, lane = tid & 31;
    int r4 = lane >> 2, c4 = lane & 3;
    int qt = blockIdx.x & 7;
    int bh = blockIdx.x >> 3;
    int h = bh & 7, b = bh >> 3;
    size_t base = (size_t)bh * S * HD;
    int qw = qt * 128 + w * 16;

    // Q fragments from global (half2 contiguous)
    unsigned qa[4][4];
    {
        const __half* qb = g_q + base + (size_t)qw * HD;
        #pragma unroll
        for (int kk = 0; kk < 4; kk++) {
            qa[kk][0] = *(const unsigned*)&qb[r4 * 64 + kk * 16 + 2 * c4];
            qa[kk][1] = *(const unsigned*)&qb[(r4 + 8) * 64 + kk * 16 + 2 * c4];
            qa[kk][2] = *(const unsigned*)&qb[r4 * 64 + kk * 16 + 2 * c4 + 8];
            qa[kk][3] = *(const unsigned*)&qb[(r4 + 8) * 64 + kk * 16 + 2 * c4 + 8];
        }
    }

    float o[8][4];
    #pragma unroll
    for (int nt = 0; nt < 8; nt++)
        #pragma unroll
        for (int j = 0; j < 4; j++) o[nt][j] = 0.f;
    float m0 = -1e30f, m1 = -1e30f, l0 = 0.f, l1 = 0.f;

    const float* mrow0 = mask + ((size_t)h * S + qw + r4) * S;
    const float* mrow1 = mrow0 + (size_t)8 * S;
    __half* sPw = sP + w * 16 * HP;

    for (int kt = 0; kt < S / 64; kt++) {
        __syncthreads();
        const __half* gk = g_k + base + (size_t)kt * 64 * 64;
        const __half* gv = g_v + base + (size_t)kt * 64 * 64;
        #pragma unroll
        for (int t = 0; t < 4; t++) {
            int idx = tid + t * 256;          // 1024 quads
            int key = idx >> 4, c = (idx & 15) * 4;
            uint2 kq = *(const uint2*)&gk[key * 64 + c];
            *(uint2*)&sK[key * HP + c] = kq;
            uint2 vq = *(const uint2*)&gv[key * 64 + c];
            const __half* vh = (const __half*)&vq;
            sVT[(c + 0) * HP + key] = vh[0];
            sVT[(c + 1) * HP + key] = vh[1];
            sVT[(c + 2) * HP + key] = vh[2];
            sVT[(c + 3) * HP + key] = vh[3];
        }
        __syncthreads();

        // energy = Q K^T
        float e[8][4];
        #pragma unroll
        for (int nt = 0; nt < 8; nt++) {
            #pragma unroll
            for (int j = 0; j < 4; j++) e[nt][j] = 0.f;
            #pragma unroll
            for (int kk = 0; kk < 4; kk++) {
                const __half* bp = &sK[(nt * 8 + r4) * HP + kk * 16 + 2 * c4];
                unsigned b0 = *(const unsigned*)bp;
                unsigned b1 = *(const unsigned*)(bp + 8);
                mma_f16(e[nt], qa[kk], b0, b1);
            }
        }

        // mask * scale
        int kb = kt * 64;
        #pragma unroll
        for (int nt = 0; nt < 8; nt++) {
            float2 mm0 = *(const float2*)&mrow0[kb + nt * 8 + 2 * c4];
            float2 mm1 = *(const float2*)&mrow1[kb + nt * 8 + 2 * c4];
            e[nt][0] *= mm0.x * SCALE;
            e[nt][1] *= mm0.y * SCALE;
            e[nt][2] *= mm1.x * SCALE;
            e[nt][3] *= mm1.y * SCALE;
        }

        // online softmax
        float rm0 = -1e30f, rm1 = -1e30f;
        #pragma unroll
        for (int nt = 0; nt < 8; nt++) {
            rm0 = fmaxf(rm0, fmaxf(e[nt][0], e[nt][1]));
            rm1 = fmaxf(rm1, fmaxf(e[nt][2], e[nt][3]));
        }
        rm0 = fmaxf(rm0, __shfl_xor_sync(0xffffffffu, rm0, 1));
        rm0 = fmaxf(rm0, __shfl_xor_sync(0xffffffffu, rm0, 2));
        rm1 = fmaxf(rm1, __shfl_xor_sync(0xffffffffu, rm1, 1));
        rm1 = fmaxf(rm1, __shfl_xor_sync(0xffffffffu, rm1, 2));
        float mn0 = fmaxf(m0, rm0), mn1 = fmaxf(m1, rm1);
        float a0 = __expf(m0 - mn0), a1 = __expf(m1 - mn1);
        float rs0 = 0.f, rs1 = 0.f;
        #pragma unroll
        for (int nt = 0; nt < 8; nt++) {
            e[nt][0] = __expf(e[nt][0] - mn0);
            e[nt][1] = __expf(e[nt][1] - mn0);
            e[nt][2] = __expf(e[nt][2] - mn1);
            e[nt][3] = __expf(e[nt][3] - mn1);
            rs0 += e[nt][0] + e[nt][1];
            rs1 += e[nt][2] + e[nt][3];
        }
        rs0 += __shfl_xor_sync(0xffffffffu, rs0, 1);
        rs0 += __shfl_xor_sync(0xffffffffu, rs0, 2);
        rs1 += __shfl_xor_sync(0xffffffffu, rs1, 1);
        rs1 += __shfl_xor_sync(0xffffffffu, rs1, 2);
        l0 = l0 * a0 + rs0;
        l1 = l1 * a1 + rs1;
        m0 = mn0; m1 = mn1;

        // P -> half smem; rescale O
        #pragma unroll
        for (int nt = 0; nt < 8; nt++) {
            *(__half2*)&sPw[r4 * HP + nt * 8 + 2 * c4] = __floats2half2_rn(e[nt][0], e[nt][1]);
            *(__half2*)&sPw[(r4 + 8) * HP + nt * 8 + 2 * c4] = __floats2half2_rn(e[nt][2], e[nt][3]);
            o[nt][0] *= a0; o[nt][1] *= a0;
            o[nt][2] *= a1; o[nt][3] *= a1;
        }
        __syncwarp();

        // O += P V
        #pragma unroll
        for (int kk = 0; kk < 4; kk++) {
            unsigned pa[4];
            pa[0] = *(const unsigned*)&sPw[r4 * HP + kk * 16 + 2 * c4];
            pa[1] = *(const unsigned*)&sPw[(r4 + 8) * HP + kk * 16 + 2 * c4];
            pa[2] = *(const unsigned*)&sPw[r4 * HP + kk * 16 + 2 * c4 + 8];
            pa[3] = *(const unsigned*)&sPw[(r4 + 8) * HP + kk * 16 + 2 * c4 + 8];
            #pragma unroll
            for (int nt = 0; nt < 8; nt++) {
                const __half* bp = &sVT[(nt * 8 + r4) * HP + kk * 16 + 2 * c4];
                unsigned b0 = *(const unsigned*)bp;
                unsigned b1 = *(const unsigned*)(bp + 8);
                mma_f16(o[nt], pa, b0, b1);
            }
        }
        __syncwarp();
    }

    float inv0 = 1.f / l0, inv1 = 1.f / l1;
    size_t ob0 = ((size_t)(b * S + qw + r4)) * D + h * 64;
    size_t ob1 = ((size_t)(b * S + qw + r4 + 8)) * D + h * 64;
    #pragma unroll
    for (int nt = 0; nt < 8; nt++) {
        *(__half2*)&g_att[ob0 + nt * 8 + 2 * c4] = __floats2half2_rn(o[nt][0] * inv0, o[nt][1] * inv0);
        *(__half2*)&g_att[ob1 + nt * 8 + 2 * c4] = __floats2half2_rn(o[nt][2] * inv1, o[nt][3] * inv1);
    }
}

// ---------------- kernel 6: out = att @ Wo^T + bo via fp16 mma ----------------
__global__ void __launch_bounds__(256, 2) k_proj(const float* __restrict__ Wo,
                                                 const float* __restrict__ bo,
                                                 float* __restrict__ out) {
    extern __shared__ __half smh[];
    __half* sA = smh;                 // 128 x 72
    __half* sB = smh + 128 * HP;      // 64 x 72
    int tid = threadIdx.x;
    int w = tid >> 5, lane = tid & 31;
    int r4 = lane >> 2, c4 = lane & 3;
    int m0 = blockIdx.x * 128;
    int n0 = blockIdx.y * 64;

    float acc[8][4];
    #pragma unroll
    for (int nt = 0; nt < 8; nt++)
        #pragma unroll
        for (int j = 0; j < 4; j++) acc[nt][j] = 0.f;

    for (int k0 = 0; k0 < D; k0 += 64) {
        __syncthreads();
        #pragma unroll
        for (int t = 0; t < 8; t++) {
            int idx = tid + t * 256;
            int r = idx >> 4, c = (idx & 15) * 4;
            uint2 q = *(const uint2*)&g_att[(size_t)(m0 + r) * D + k0 + c];
            *(uint2*)&sA[r * HP + c] = q;
        }
        #pragma unroll
        for (int t = 0; t < 4; t++) {
            int idx = tid + t * 256;
            int r = idx >> 4, c = (idx & 15) * 4;
            float4 v = *(const float4*)&Wo[(size_t)(n0 + r) * D + k0 + c];
            *(__half2*)&sB[r * HP + c] = __floats2half2_rn(v.x, v.y);
            *(__half2*)&sB[r * HP + c + 2] = __floats2half2_rn(v.z, v.w);
        }
        __syncthreads();

        const __half* Aw = sA + (w * 16) * HP;
        unsigned af[4][4];
        #pragma unroll
        for (int kk = 0; kk < 4; kk++) {
            af[kk][0] = *(const unsigned*)&Aw[r4 * HP + kk * 16 + 2 * c4];
            af[kk][1] = *(const unsigned*)&Aw[(r4 + 8) * HP + kk * 16 + 2 * c4];
            af[kk][2] = *(const unsigned*)&Aw[r4 * HP + kk * 16 + 2 * c4 + 8];
            af[kk][3] = *(const unsigned*)&Aw[(r4 + 8) * HP + kk * 16 + 2 * c4 + 8];
        }
        #pragma unroll
        for (int nt = 0; nt < 8; nt++) {
            #pragma unroll
            for (int kk = 0; kk < 4; kk++) {
                const __half* bp = &sB[(nt * 8 + r4) * HP + kk * 16 + 2 * c4];
                unsigned b0 = *(const unsigned*)bp;
                unsigned b1 = *(const unsigned*)(bp + 8);
                mma_f16(acc[nt], af[kk], b0, b1);
            }
        }
    }

    int row0 = m0 + w * 16 + r4;
    #pragma unroll
    for (int nt = 0; nt < 8; nt++) {
        int n = n0 + nt * 8 + 2 * c4;
        float2 bb = *(const float2*)&bo[n];
        float2 v0, v1;
        v0.x = acc[nt][0] + bb.x; v0.y = acc[nt][1] + bb.y;
        v1.x = acc[nt][2] + bb.x; v1.y = acc[nt][3] + bb.y;
        *(float2*)&out[(size_t)row0 * D + n] = v0;
        *(float2*)&out[(size_t)(row0 + 8) * D + n] = v1;
    }
}

// ---------------- launch ----------------
extern "C" void kernel_launch(void* const* d_in, const int* in_sizes, int n_in,
                              void* d_out, int out_size) {
    const int*   x   = (const int*)d_in[0];
    const float* emb = (const float*)d_in[1];
    const float* Wq  = (const float*)d_in[2];
    const float* Wk  = (const float*)d_in[3];
    const float* Wv  = (const float*)d_in[4];
    const float* Wo  = (const float*)d_in[5];
    const float* bo  = (const float*)d_in[6];
    const float* Wc  = (const float*)d_in[7];
    const float* bc  = (const float*)d_in[8];
    float* out = (float*)d_out;
    float* maskout = out + (size_t)B * S * D;

    k_pe<<<S, 256>>>();
    k_embed<<<BS, 128>>>(x, emb, Wc, bc);
    k_norm<<<B, S>>>();
    dim3 mg(S, B);
    k_mask<<<mg, 256>>>(maskout);

    size_t qkv_smem = (128 * HP + 3 * 64 * HP) * sizeof(__half);   // 46080 B
    cudaFuncSetAttribute(k_qkv, cudaFuncAttributeMaxDynamicSharedMemorySize, (int)qkv_smem);
    dim3 qg(BS / 128, H);
    k_qkv<<<qg, 256, qkv_smem>>>(Wq, Wk, Wv);

    size_t attn_smem = (64 * HP + 64 * HP + 128 * HP) * sizeof(__half);  // 36864 B
    cudaFuncSetAttribute(k_attn, cudaFuncAttributeMaxDynamicSharedMemorySize, (int)attn_smem);
    k_attn<<<B * H * (S / 128), 256, attn_smem>>>(maskout);

    size_t proj_smem = (128 * HP + 64 * HP) * sizeof(__half);      // 27648 B
    cudaFuncSetAttribute(k_proj, cudaFuncAttributeMaxDynamicSharedMemorySize, (int)proj_smem);
    dim3 pg(BS / 128, D / 64);
    k_proj<<<pg, 256, proj_smem>>>(Wo, bo, out);
}

// round 7
// speedup vs baseline: 8.8263x; 1.2243x over previous
#include <cuda_runtime.h>
#include <cuda_fp16.h>
#include <math.h>

#define B 8
#define S 1024
#define D 512
#define H 8
#define HD 64
#define BS (B*S)
#define SCALE 0.044194173824159216f  // 1/sqrt(512)
#define HP 72   // half-element row pad: ldmatrix row banks 4r%32 conflict-free

// ---------------- scratch (static device globals; no allocation) ----------------
__device__ float  g_pe[S * D];
__device__ float  g_w[BS];
__device__ __half g_hh[BS * D];
__device__ __half g_q[B * H * S * HD];   // [b,h,s,d]
__device__ __half g_k[B * H * S * HD];
__device__ __half g_v[B * H * S * HD];
__device__ __half g_att[BS * D];

// ---------------- helpers ----------------
__device__ __forceinline__ void mma_f16(float d[4], const unsigned a[4],
                                        unsigned b0, unsigned b1) {
    asm("mma.sync.aligned.m16n8k16.row.col.f32.f16.f16.f32 "
        "{%0,%1,%2,%3}, {%4,%5,%6,%7}, {%8,%9}, {%0,%1,%2,%3};"
        : "+f"(d[0]), "+f"(d[1]), "+f"(d[2]), "+f"(d[3])
        : "r"(a[0]), "r"(a[1]), "r"(a[2]), "r"(a[3]), "r"(b0), "r"(b1));
}
__device__ __forceinline__ void ldmx4(unsigned r[4], unsigned addr) {
    asm volatile("ldmatrix.sync.aligned.m8n8.x4.shared.b16 {%0,%1,%2,%3}, [%4];"
        : "=r"(r[0]), "=r"(r[1]), "=r"(r[2]), "=r"(r[3]) : "r"(addr));
}
__device__ __forceinline__ void ldmx4t(unsigned r[4], unsigned addr) {
    asm volatile("ldmatrix.sync.aligned.m8n8.x4.trans.shared.b16 {%0,%1,%2,%3}, [%4];"
        : "=r"(r[0]), "=r"(r[1]), "=r"(r[2]), "=r"(r[3]) : "r"(addr));
}
__device__ __forceinline__ unsigned h2u(float a, float b) {
    __half2 h = __floats2half2_rn(a, b);
    return *(unsigned*)&h;
}

// ---------------- kernel 0: PE table ----------------
__global__ void k_pe() {
    int s = blockIdx.x;
    const float c = -logf(10000.0f) / (float)D;
    #pragma unroll
    for (int t = 0; t < 2; t++) {
        int d = threadIdx.x + t * 256;
        int i2 = d & ~1;
        float ang = (float)s * expf(c * (float)i2);
        g_pe[s * D + d] = (d & 1) ? cosf(ang) : sinf(ang);
    }
}

// ---------------- kernel 1: h = emb[x]+PE, width dot ----------------
__global__ void __launch_bounds__(128) k_embed(const int* __restrict__ x,
                                               const float* __restrict__ emb,
                                               const float* __restrict__ Wc,
                                               const float* __restrict__ bc) {
    int bs = blockIdx.x;
    int s = bs & (S - 1);
    int tok = x[bs];
    int t = threadIdx.x;
    const float4* e4 = (const float4*)(emb + (size_t)tok * D);
    const float4* p4 = (const float4*)(g_pe + (size_t)s * D);
    const float4* w4 = (const float4*)Wc;

    float4 e = e4[t], p = p4[t], w = w4[t];
    float4 hv;
    hv.x = e.x + p.x; hv.y = e.y + p.y; hv.z = e.z + p.z; hv.w = e.w + p.w;
    __half2* hh = (__half2*)(g_hh + (size_t)bs * D + t * 4);
    hh[0] = __floats2half2_rn(hv.x, hv.y);
    hh[1] = __floats2half2_rn(hv.z, hv.w);
    float wsum = hv.x * w.x + hv.y * w.y + hv.z * w.z + hv.w * w.w;

    #pragma unroll
    for (int off = 16; off; off >>= 1)
        wsum += __shfl_xor_sync(0xffffffffu, wsum, off);
    __shared__ float red[4];
    if ((t & 31) == 0) red[t >> 5] = wsum;
    __syncthreads();
    if (t == 0)
        g_w[bs] = red[0] + red[1] + red[2] + red[3] + bc[0];
}

// ---------------- kernel 2: per-batch min-max normalize ----------------
__global__ void k_norm() {
    int b = blockIdx.x;
    int t = threadIdx.x;
    float v = g_w[b * S + t];
    float mn = v, mx = v;
    __shared__ float smin[32], smax[32];
    #pragma unroll
    for (int off = 16; off; off >>= 1) {
        mn = fminf(mn, __shfl_xor_sync(0xffffffffu, mn, off));
        mx = fmaxf(mx, __shfl_xor_sync(0xffffffffu, mx, off));
    }
    if ((t & 31) == 0) { smin[t >> 5] = mn; smax[t >> 5] = mx; }
    __syncthreads();
    if (t < 32) {
        mn = smin[t]; mx = smax[t];
        #pragma unroll
        for (int off = 16; off; off >>= 1) {
            mn = fminf(mn, __shfl_xor_sync(0xffffffffu, mn, off));
            mx = fmaxf(mx, __shfl_xor_sync(0xffffffffu, mx, off));
        }
        if (t == 0) { smin[0] = mn; smax[0] = mx; }
    }
    __syncthreads();
    float lo = smin[0], hi = smax[0];
    g_w[b * S + t] = (v - lo) / (hi - lo);
}

// ---------------- kernel 3: mask ----------------
__global__ void __launch_bounds__(256) k_mask(float* __restrict__ mout) {
    int i = blockIdx.x, b = blockIdx.y;
    float w = g_w[b * S + i];
    float4* mrow4 = (float4*)(mout + ((size_t)b * S + i) * S);
    bool lower = (i < S / 2);
    int j0 = threadIdx.x * 4;
    float r[4];
    #pragma unroll
    for (int u = 0; u < 4; u++) {
        int j = j0 + u;
        int idx = (S / 2 - 1 - i + j) & (S - 1);
        float origin = (idx < S / 2) ? (1.0f - (float)idx * (1.0f / (float)(S / 2 - 1)))
                                     : ((float)(idx - S / 2) * (1.0f / (float)(S / 2 - 1)));
        bool cmp = (idx >= j);
        bool move = lower ? cmp : !cmp;
        float val = 0.f;
        if (move) {
            float z = (origin - w) * 100.f;
            val = 1.f / (1.f + __expf(z));
        }
        r[u] = val;
    }
    mrow4[threadIdx.x] = make_float4(r[0], r[1], r[2], r[3]);
}

// ---------------- kernel 4: QKV via fp16 mma ----------------
__global__ void __launch_bounds__(256) k_qkv(const float* __restrict__ Wq,
                                             const float* __restrict__ Wk,
                                             const float* __restrict__ Wv) {
    extern __shared__ __half smh[];
    __half* sA = smh;                 // 128 x 72
    __half* sB = smh + 128 * HP;      // 3 x 64 x 72
    int tid = threadIdx.x;
    int w = tid >> 5, lane = tid & 31;
    int r4 = lane >> 2, c4 = lane & 3;
    int m0 = blockIdx.x * 128;
    int h = blockIdx.y;

    #pragma unroll
    for (int t = 0; t < 8; t++) {
        int idx = tid + t * 256;
        int r = idx >> 4, c = (idx & 15) * 4;
        uint2 q = *(const uint2*)&g_hh[(size_t)(m0 + r) * D + h * 64 + c];
        *(uint2*)&sA[r * HP + c] = q;
    }
    const float* Ws[3] = {Wq, Wk, Wv};
    #pragma unroll
    for (int wi = 0; wi < 3; wi++) {
        #pragma unroll
        for (int t = 0; t < 4; t++) {
            int idx = tid + t * 256;
            int r = idx >> 4, c = (idx & 15) * 4;
            float4 v = *(const float4*)&Ws[wi][(size_t)r * 64 + c];
            *(__half2*)&sB[(wi * 64 + r) * HP + c] = __floats2half2_rn(v.x, v.y);
            *(__half2*)&sB[(wi * 64 + r) * HP + c + 2] = __floats2half2_rn(v.z, v.w);
        }
    }
    __syncthreads();

    const __half* Aw = sA + (w * 16) * HP;
    unsigned af[4][4];
    #pragma unroll
    for (int kk = 0; kk < 4; kk++) {
        af[kk][0] = *(const unsigned*)&Aw[r4 * HP + kk * 16 + 2 * c4];
        af[kk][1] = *(const unsigned*)&Aw[(r4 + 8) * HP + kk * 16 + 2 * c4];
        af[kk][2] = *(const unsigned*)&Aw[r4 * HP + kk * 16 + 2 * c4 + 8];
        af[kk][3] = *(const unsigned*)&Aw[(r4 + 8) * HP + kk * 16 + 2 * c4 + 8];
    }

    int row0 = m0 + w * 16 + r4;
    __half* outs[3] = {g_q, g_k, g_v};
    #pragma unroll
    for (int wi = 0; wi < 3; wi++) {
        float acc[8][4];
        #pragma unroll
        for (int nt = 0; nt < 8; nt++) {
            #pragma unroll
            for (int j = 0; j < 4; j++) acc[nt][j] = 0.f;
            #pragma unroll
            for (int kk = 0; kk < 4; kk++) {
                const __half* bp = &sB[(wi * 64 + nt * 8 + r4) * HP + kk * 16 + 2 * c4];
                unsigned b0 = *(const unsigned*)bp;
                unsigned b1 = *(const unsigned*)(bp + 8);
                mma_f16(acc[nt], af[kk], b0, b1);
            }
        }
        int b0r = row0 >> 10, s0 = row0 & (S - 1);
        int b1r = (row0 + 8) >> 10, s1 = (row0 + 8) & (S - 1);
        size_t q0 = (((size_t)b0r * H + h) * S + s0) * HD;
        size_t q1 = (((size_t)b1r * H + h) * S + s1) * HD;
        __half* op = outs[wi];
        #pragma unroll
        for (int nt = 0; nt < 8; nt++) {
            *(__half2*)&op[q0 + nt * 8 + 2 * c4] = __floats2half2_rn(acc[nt][0], acc[nt][1]);
            *(__half2*)&op[q1 + nt * 8 + 2 * c4] = __floats2half2_rn(acc[nt][2], acc[nt][3]);
        }
    }
}

// ---------------- kernel 5: fp16 mma flash attention (ldmatrix, no P smem) ----------------
__global__ void __launch_bounds__(256, 2) k_attn(const float* __restrict__ mask) {
    extern __shared__ __half smh[];
    __half* sK = smh;                 // [key][d] 64 x 72
    __half* sV = smh + 64 * HP;       // [key][d] 64 x 72

    int tid = threadIdx.x;
    int w = tid >> 5, lane = tid & 31;
    int r4 = lane >> 2, c4 = lane & 3;
    int qt = blockIdx.x & 7;
    int bh = blockIdx.x >> 3;
    int h = bh & 7, b = bh >> 3;
    size_t base = (size_t)bh * S * HD;
    int qw = qt * 128 + w * 16;

    unsigned sK_u = (unsigned)__cvta_generic_to_shared(sK);
    unsigned sV_u = (unsigned)__cvta_generic_to_shared(sV);
    // K ldmatrix row base: row = lane&7, col-block = (lane>>3)*8
    unsigned krow = ((lane & 7) * HP + ((lane >> 3) << 3)) * 2;
    // V trans ldmatrix: row = ((lane>>3)&1)*8 + (lane&7), col-block = (lane>>4)*8
    unsigned vrow = ((((lane >> 3) & 1) * 8 + (lane & 7)) * HP + ((lane >> 4) << 3)) * 2;

    // Q fragments from global
    unsigned qa[4][4];
    {
        const __half* qb = g_q + base + (size_t)qw * HD;
        #pragma unroll
        for (int kk = 0; kk < 4; kk++) {
            qa[kk][0] = *(const unsigned*)&qb[r4 * 64 + kk * 16 + 2 * c4];
            qa[kk][1] = *(const unsigned*)&qb[(r4 + 8) * 64 + kk * 16 + 2 * c4];
            qa[kk][2] = *(const unsigned*)&qb[r4 * 64 + kk * 16 + 2 * c4 + 8];
            qa[kk][3] = *(const unsigned*)&qb[(r4 + 8) * 64 + kk * 16 + 2 * c4 + 8];
        }
    }

    float o[8][4];
    #pragma unroll
    for (int nt = 0; nt < 8; nt++)
        #pragma unroll
        for (int j = 0; j < 4; j++) o[nt][j] = 0.f;
    float m0 = -1e30f, m1 = -1e30f, l0 = 0.f, l1 = 0.f;

    const float* mrow0 = mask + ((size_t)h * S + qw + r4) * S;
    const float* mrow1 = mrow0 + (size_t)8 * S;

    for (int kt = 0; kt < S / 64; kt++) {
        __syncthreads();
        const __half* gk = g_k + base + (size_t)kt * 64 * 64;
        const __half* gv = g_v + base + (size_t)kt * 64 * 64;
        #pragma unroll
        for (int t = 0; t < 4; t++) {
            int idx = tid + t * 256;
            int key = idx >> 4, c = (idx & 15) * 4;
            *(uint2*)&sK[key * HP + c] = *(const uint2*)&gk[key * 64 + c];
            *(uint2*)&sV[key * HP + c] = *(const uint2*)&gv[key * 64 + c];
        }
        __syncthreads();

        // energy = Q K^T  (B-frags via ldmatrix.x4)
        float e[8][4];
        #pragma unroll
        for (int nt = 0; nt < 8; nt++) {
            #pragma unroll
            for (int j = 0; j < 4; j++) e[nt][j] = 0.f;
            unsigned kb0 = sK_u + nt * 8 * HP * 2 + krow;
            unsigned bf[4], bf2[4];
            ldmx4(bf, kb0);            // d 0..31  -> kk 0,1
            ldmx4(bf2, kb0 + 64);      // d 32..63 -> kk 2,3
            mma_f16(e[nt], qa[0], bf[0], bf[1]);
            mma_f16(e[nt], qa[1], bf[2], bf[3]);
            mma_f16(e[nt], qa[2], bf2[0], bf2[1]);
            mma_f16(e[nt], qa[3], bf2[2], bf2[3]);
        }

        // mask * scale
        int kb = kt * 64;
        #pragma unroll
        for (int nt = 0; nt < 8; nt++) {
            float2 mm0 = *(const float2*)&mrow0[kb + nt * 8 + 2 * c4];
            float2 mm1 = *(const float2*)&mrow1[kb + nt * 8 + 2 * c4];
            e[nt][0] *= mm0.x * SCALE;
            e[nt][1] *= mm0.y * SCALE;
            e[nt][2] *= mm1.x * SCALE;
            e[nt][3] *= mm1.y * SCALE;
        }

        // online softmax
        float rm0 = -1e30f, rm1 = -1e30f;
        #pragma unroll
        for (int nt = 0; nt < 8; nt++) {
            rm0 = fmaxf(rm0, fmaxf(e[nt][0], e[nt][1]));
            rm1 = fmaxf(rm1, fmaxf(e[nt][2], e[nt][3]));
        }
        rm0 = fmaxf(rm0, __shfl_xor_sync(0xffffffffu, rm0, 1));
        rm0 = fmaxf(rm0, __shfl_xor_sync(0xffffffffu, rm0, 2));
        rm1 = fmaxf(rm1, __shfl_xor_sync(0xffffffffu, rm1, 1));
        rm1 = fmaxf(rm1, __shfl_xor_sync(0xffffffffu, rm1, 2));
        float mn0 = fmaxf(m0, rm0), mn1 = fmaxf(m1, rm1);
        float a0 = __expf(m0 - mn0), a1 = __expf(m1 - mn1);
        float rs0 = 0.f, rs1 = 0.f;
        #pragma unroll
        for (int nt = 0; nt < 8; nt++) {
            e[nt][0] = __expf(e[nt][0] - mn0);
            e[nt][1] = __expf(e[nt][1] - mn0);
            e[nt][2] = __expf(e[nt][2] - mn1);
            e[nt][3] = __expf(e[nt][3] - mn1);
            rs0 += e[nt][0] + e[nt][1];
            rs1 += e[nt][2] + e[nt][3];
        }
        rs0 += __shfl_xor_sync(0xffffffffu, rs0, 1);
        rs0 += __shfl_xor_sync(0xffffffffu, rs0, 2);
        rs1 += __shfl_xor_sync(0xffffffffu, rs1, 1);
        rs1 += __shfl_xor_sync(0xffffffffu, rs1, 2);
        l0 = l0 * a0 + rs0;
        l1 = l1 * a1 + rs1;
        m0 = mn0; m1 = mn1;

        // rescale O
        #pragma unroll
        for (int nt = 0; nt < 8; nt++) {
            o[nt][0] *= a0; o[nt][1] *= a0;
            o[nt][2] *= a1; o[nt][3] *= a1;
        }

        // O += P V : P accumulator -> A fragments directly; V via ldmatrix.trans
        #pragma unroll
        for (int kk = 0; kk < 4; kk++) {
            unsigned pa[4];
            pa[0] = h2u(e[2 * kk][0], e[2 * kk][1]);
            pa[1] = h2u(e[2 * kk][2], e[2 * kk][3]);
            pa[2] = h2u(e[2 * kk + 1][0], e[2 * kk + 1][1]);
            pa[3] = h2u(e[2 * kk + 1][2], e[2 * kk + 1][3]);
            #pragma unroll
            for (int ntp = 0; ntp < 4; ntp++) {
                unsigned vf[4];
                ldmx4t(vf, sV_u + (kk * 16 * HP + ntp * 16) * 2 + vrow);
                mma_f16(o[2 * ntp], pa, vf[0], vf[1]);
                mma_f16(o[2 * ntp + 1], pa, vf[2], vf[3]);
            }
        }
    }

    float inv0 = 1.f / l0, inv1 = 1.f / l1;
    size_t ob0 = ((size_t)(b * S + qw + r4)) * D + h * 64;
    size_t ob1 = ((size_t)(b * S + qw + r4 + 8)) * D + h * 64;
    #pragma unroll
    for (int nt = 0; nt < 8; nt++) {
        *(__half2*)&g_att[ob0 + nt * 8 + 2 * c4] = __floats2half2_rn(o[nt][0] * inv0, o[nt][1] * inv0);
        *(__half2*)&g_att[ob1 + nt * 8 + 2 * c4] = __floats2half2_rn(o[nt][2] * inv1, o[nt][3] * inv1);
    }
}

// ---------------- kernel 6: out = att @ Wo^T + bo via fp16 mma ----------------
__global__ void __launch_bounds__(256, 2) k_proj(const float* __restrict__ Wo,
                                                 const float* __restrict__ bo,
                                                 float* __restrict__ out) {
    extern __shared__ __half smh[];
    __half* sA = smh;                 // 128 x 72
    __half* sB = smh + 128 * HP;      // 64 x 72
    int tid = threadIdx.x;
    int w = tid >> 5, lane = tid & 31;
    int r4 = lane >> 2, c4 = lane & 3;
    int m0 = blockIdx.x * 128;
    int n0 = blockIdx.y * 64;

    float acc[8][4];
    #pragma unroll
    for (int nt = 0; nt < 8; nt++)
        #pragma unroll
        for (int j = 0; j < 4; j++) acc[nt][j] = 0.f;

    for (int k0 = 0; k0 < D; k0 += 64) {
        __syncthreads();
        #pragma unroll
        for (int t = 0; t < 8; t++) {
            int idx = tid + t * 256;
            int r = idx >> 4, c = (idx & 15) * 4;
            *(uint2*)&sA[r * HP + c] = *(const uint2*)&g_att[(size_t)(m0 + r) * D + k0 + c];
        }
        #pragma unroll
        for (int t = 0; t < 4; t++) {
            int idx = tid + t * 256;
            int r = idx >> 4, c = (idx & 15) * 4;
            float4 v = *(const float4*)&Wo[(size_t)(n0 + r) * D + k0 + c];
            *(__half2*)&sB[r * HP + c] = __floats2half2_rn(v.x, v.y);
            *(__half2*)&sB[r * HP + c + 2] = __floats2half2_rn(v.z, v.w);
        }
        __syncthreads();

        const __half* Aw = sA + (w * 16) * HP;
        unsigned af[4][4];
        #pragma unroll
        for (int kk = 0; kk < 4; kk++) {
            af[kk][0] = *(const unsigned*)&Aw[r4 * HP + kk * 16 + 2 * c4];
            af[kk][1] = *(const unsigned*)&Aw[(r4 + 8) * HP + kk * 16 + 2 * c4];
            af[kk][2] = *(const unsigned*)&Aw[r4 * HP + kk * 16 + 2 * c4 + 8];
            af[kk][3] = *(const unsigned*)&Aw[(r4 + 8) * HP + kk * 16 + 2 * c4 + 8];
        }
        #pragma unroll
        for (int nt = 0; nt < 8; nt++) {
            #pragma unroll
            for (int kk = 0; kk < 4; kk++) {
                const __half* bp = &sB[(nt * 8 + r4) * HP + kk * 16 + 2 * c4];
                unsigned b0 = *(const unsigned*)bp;
                unsigned b1 = *(const unsigned*)(bp + 8);
                mma_f16(acc[nt], af[kk], b0, b1);
            }
        }
    }

    int row0 = m0 + w * 16 + r4;
    #pragma unroll
    for (int nt = 0; nt < 8; nt++) {
        int n = n0 + nt * 8 + 2 * c4;
        float2 bb = *(const float2*)&bo[n];
        float2 v0, v1;
        v0.x = acc[nt][0] + bb.x; v0.y = acc[nt][1] + bb.y;
        v1.x = acc[nt][2] + bb.x; v1.y = acc[nt][3] + bb.y;
        *(float2*)&out[(size_t)row0 * D + n] = v0;
        *(float2*)&out[(size_t)(row0 + 8) * D + n] = v1;
    }
}

// ---------------- launch ----------------
extern "C" void kernel_launch(void* const* d_in, const int* in_sizes, int n_in,
                              void* d_out, int out_size) {
    const int*   x   = (const int*)d_in[0];
    const float* emb = (const float*)d_in[1];
    const float* Wq  = (const float*)d_in[2];
    const float* Wk  = (const float*)d_in[3];
    const float* Wv  = (const float*)d_in[4];
    const float* Wo  = (const float*)d_in[5];
    const float* bo  = (const float*)d_in[6];
    const float* Wc  = (const float*)d_in[7];
    const float* bc  = (const float*)d_in[8];
    float* out = (float*)d_out;
    float* maskout = out + (size_t)B * S * D;

    k_pe<<<S, 256>>>();
    k_embed<<<BS, 128>>>(x, emb, Wc, bc);
    k_norm<<<B, S>>>();
    dim3 mg(S, B);
    k_mask<<<mg, 256>>>(maskout);

    size_t qkv_smem = (128 * HP + 3 * 64 * HP) * sizeof(__half);
    cudaFuncSetAttribute(k_qkv, cudaFuncAttributeMaxDynamicSharedMemorySize, (int)qkv_smem);
    dim3 qg(BS / 128, H);
    k_qkv<<<qg, 256, qkv_smem>>>(Wq, Wk, Wv);

    size_t attn_smem = (64 * HP + 64 * HP) * sizeof(__half);   // 18432 B
    cudaFuncSetAttribute(k_attn, cudaFuncAttributeMaxDynamicSharedMemorySize, (int)attn_smem);
    k_attn<<<B * H * (S / 128), 256, attn_smem>>>(maskout);

    size_t proj_smem = (128 * HP + 64 * HP) * sizeof(__half);
    cudaFuncSetAttribute(k_proj, cudaFuncAttributeMaxDynamicSharedMemorySize, (int)proj_smem);
    dim3 pg(BS / 128, D / 64);
    k_proj<<<pg, 256, proj_smem>>>(Wo, bo, out);
}

// round 8
// speedup vs baseline: 9.4467x; 1.0703x over previous
#include <cuda_runtime.h>
#include <cuda_fp16.h>
#include <math.h>

#define B 8
#define S 1024
#define D 512
#define H 8
#define HD 64
#define BS (B*S)
#define SCALE 0.044194173824159216f  // 1/sqrt(512)
#define HP 72   // half-element row pad: ldmatrix row banks 4r%32 conflict-free

// ---------------- scratch (static device globals; no allocation) ----------------
__device__ float  g_pe[S * D];
__device__ float  g_w[BS];
__device__ __half g_hh[BS * D];
__device__ __half g_q[B * H * S * HD];   // [b,h,s,d]
__device__ __half g_k[B * H * S * HD];
__device__ __half g_v[B * H * S * HD];
__device__ __half g_att[BS * D];

// ---------------- helpers ----------------
__device__ __forceinline__ void mma_f16(float d[4], const unsigned a[4],
                                        unsigned b0, unsigned b1) {
    asm("mma.sync.aligned.m16n8k16.row.col.f32.f16.f16.f32 "
        "{%0,%1,%2,%3}, {%4,%5,%6,%7}, {%8,%9}, {%0,%1,%2,%3};"
        : "+f"(d[0]), "+f"(d[1]), "+f"(d[2]), "+f"(d[3])
        : "r"(a[0]), "r"(a[1]), "r"(a[2]), "r"(a[3]), "r"(b0), "r"(b1));
}
__device__ __forceinline__ void ldmx4(unsigned r[4], unsigned addr) {
    asm volatile("ldmatrix.sync.aligned.m8n8.x4.shared.b16 {%0,%1,%2,%3}, [%4];"
        : "=r"(r[0]), "=r"(r[1]), "=r"(r[2]), "=r"(r[3]) : "r"(addr));
}
__device__ __forceinline__ void ldmx4t(unsigned r[4], unsigned addr) {
    asm volatile("ldmatrix.sync.aligned.m8n8.x4.trans.shared.b16 {%0,%1,%2,%3}, [%4];"
        : "=r"(r[0]), "=r"(r[1]), "=r"(r[2]), "=r"(r[3]) : "r"(addr));
}
__device__ __forceinline__ unsigned h2u(float a, float b) {
    __half2 h = __floats2half2_rn(a, b);
    return *(unsigned*)&h;
}
__device__ __forceinline__ void cpa16(unsigned dst, const void* src) {
    asm volatile("cp.async.cg.shared.global [%0], [%1], 16;" :: "r"(dst), "l"(src));
}
#define CP_COMMIT() asm volatile("cp.async.commit_group;")
#define CP_WAIT0()  asm volatile("cp.async.wait_group 0;")

// ---------------- kernel 0: PE table ----------------
__global__ void k_pe() {
    int s = blockIdx.x;
    const float c = -logf(10000.0f) / (float)D;
    #pragma unroll
    for (int t = 0; t < 2; t++) {
        int d = threadIdx.x + t * 256;
        int i2 = d & ~1;
        float ang = (float)s * expf(c * (float)i2);
        g_pe[s * D + d] = (d & 1) ? cosf(ang) : sinf(ang);
    }
}

// ---------------- kernel 1: h = emb[x]+PE, width dot ----------------
__global__ void __launch_bounds__(128) k_embed(const int* __restrict__ x,
                                               const float* __restrict__ emb,
                                               const float* __restrict__ Wc,
                                               const float* __restrict__ bc) {
    int bs = blockIdx.x;
    int s = bs & (S - 1);
    int tok = x[bs];
    int t = threadIdx.x;
    const float4* e4 = (const float4*)(emb + (size_t)tok * D);
    const float4* p4 = (const float4*)(g_pe + (size_t)s * D);
    const float4* w4 = (const float4*)Wc;

    float4 e = e4[t], p = p4[t], w = w4[t];
    float4 hv;
    hv.x = e.x + p.x; hv.y = e.y + p.y; hv.z = e.z + p.z; hv.w = e.w + p.w;
    __half2* hh = (__half2*)(g_hh + (size_t)bs * D + t * 4);
    hh[0] = __floats2half2_rn(hv.x, hv.y);
    hh[1] = __floats2half2_rn(hv.z, hv.w);
    float wsum = hv.x * w.x + hv.y * w.y + hv.z * w.z + hv.w * w.w;

    #pragma unroll
    for (int off = 16; off; off >>= 1)
        wsum += __shfl_xor_sync(0xffffffffu, wsum, off);
    __shared__ float red[4];
    if ((t & 31) == 0) red[t >> 5] = wsum;
    __syncthreads();
    if (t == 0)
        g_w[bs] = red[0] + red[1] + red[2] + red[3] + bc[0];
}

// ---------------- kernel 2: per-batch min-max normalize ----------------
__global__ void k_norm() {
    int b = blockIdx.x;
    int t = threadIdx.x;
    float v = g_w[b * S + t];
    float mn = v, mx = v;
    __shared__ float smin[32], smax[32];
    #pragma unroll
    for (int off = 16; off; off >>= 1) {
        mn = fminf(mn, __shfl_xor_sync(0xffffffffu, mn, off));
        mx = fmaxf(mx, __shfl_xor_sync(0xffffffffu, mx, off));
    }
    if ((t & 31) == 0) { smin[t >> 5] = mn; smax[t >> 5] = mx; }
    __syncthreads();
    if (t < 32) {
        mn = smin[t]; mx = smax[t];
        #pragma unroll
        for (int off = 16; off; off >>= 1) {
            mn = fminf(mn, __shfl_xor_sync(0xffffffffu, mn, off));
            mx = fmaxf(mx, __shfl_xor_sync(0xffffffffu, mx, off));
        }
        if (t == 0) { smin[0] = mn; smax[0] = mx; }
    }
    __syncthreads();
    float lo = smin[0], hi = smax[0];
    g_w[b * S + t] = (v - lo) / (hi - lo);
}

// ---------------- kernel 3: mask ----------------
__global__ void __launch_bounds__(256) k_mask(float* __restrict__ mout) {
    int i = blockIdx.x, b = blockIdx.y;
    float w = g_w[b * S + i];
    float4* mrow4 = (float4*)(mout + ((size_t)b * S + i) * S);
    bool lower = (i < S / 2);
    int j0 = threadIdx.x * 4;
    float r[4];
    #pragma unroll
    for (int u = 0; u < 4; u++) {
        int j = j0 + u;
        int idx = (S / 2 - 1 - i + j) & (S - 1);
        float origin = (idx < S / 2) ? (1.0f - (float)idx * (1.0f / (float)(S / 2 - 1)))
                                     : ((float)(idx - S / 2) * (1.0f / (float)(S / 2 - 1)));
        bool cmp = (idx >= j);
        bool move = lower ? cmp : !cmp;
        float val = 0.f;
        if (move) {
            float z = (origin - w) * 100.f;
            val = 1.f / (1.f + __expf(z));
        }
        r[u] = val;
    }
    mrow4[threadIdx.x] = make_float4(r[0], r[1], r[2], r[3]);
}

// ---------------- kernel 4: QKV via fp16 mma ----------------
__global__ void __launch_bounds__(256) k_qkv(const float* __restrict__ Wq,
                                             const float* __restrict__ Wk,
                                             const float* __restrict__ Wv) {
    extern __shared__ __half smh[];
    __half* sA = smh;                 // 128 x 72
    __half* sB = smh + 128 * HP;      // 3 x 64 x 72
    int tid = threadIdx.x;
    int w = tid >> 5, lane = tid & 31;
    int r4 = lane >> 2, c4 = lane & 3;
    int m0 = blockIdx.x * 128;
    int h = blockIdx.y;

    #pragma unroll
    for (int t = 0; t < 8; t++) {
        int idx = tid + t * 256;
        int r = idx >> 4, c = (idx & 15) * 4;
        uint2 q = *(const uint2*)&g_hh[(size_t)(m0 + r) * D + h * 64 + c];
        *(uint2*)&sA[r * HP + c] = q;
    }
    const float* Ws[3] = {Wq, Wk, Wv};
    #pragma unroll
    for (int wi = 0; wi < 3; wi++) {
        #pragma unroll
        for (int t = 0; t < 4; t++) {
            int idx = tid + t * 256;
            int r = idx >> 4, c = (idx & 15) * 4;
            float4 v = *(const float4*)&Ws[wi][(size_t)r * 64 + c];
            *(__half2*)&sB[(wi * 64 + r) * HP + c] = __floats2half2_rn(v.x, v.y);
            *(__half2*)&sB[(wi * 64 + r) * HP + c + 2] = __floats2half2_rn(v.z, v.w);
        }
    }
    __syncthreads();

    const __half* Aw = sA + (w * 16) * HP;
    unsigned af[4][4];
    #pragma unroll
    for (int kk = 0; kk < 4; kk++) {
        af[kk][0] = *(const unsigned*)&Aw[r4 * HP + kk * 16 + 2 * c4];
        af[kk][1] = *(const unsigned*)&Aw[(r4 + 8) * HP + kk * 16 + 2 * c4];
        af[kk][2] = *(const unsigned*)&Aw[r4 * HP + kk * 16 + 2 * c4 + 8];
        af[kk][3] = *(const unsigned*)&Aw[(r4 + 8) * HP + kk * 16 + 2 * c4 + 8];
    }

    int row0 = m0 + w * 16 + r4;
    __half* outs[3] = {g_q, g_k, g_v};
    #pragma unroll
    for (int wi = 0; wi < 3; wi++) {
        float acc[8][4];
        #pragma unroll
        for (int nt = 0; nt < 8; nt++) {
            #pragma unroll
            for (int j = 0; j < 4; j++) acc[nt][j] = 0.f;
            #pragma unroll
            for (int kk = 0; kk < 4; kk++) {
                const __half* bp = &sB[(wi * 64 + nt * 8 + r4) * HP + kk * 16 + 2 * c4];
                unsigned b0 = *(const unsigned*)bp;
                unsigned b1 = *(const unsigned*)(bp + 8);
                mma_f16(acc[nt], af[kk], b0, b1);
            }
        }
        int b0r = row0 >> 10, s0 = row0 & (S - 1);
        int b1r = (row0 + 8) >> 10, s1 = (row0 + 8) & (S - 1);
        size_t q0 = (((size_t)b0r * H + h) * S + s0) * HD;
        size_t q1 = (((size_t)b1r * H + h) * S + s1) * HD;
        __half* op = outs[wi];
        #pragma unroll
        for (int nt = 0; nt < 8; nt++) {
            *(__half2*)&op[q0 + nt * 8 + 2 * c4] = __floats2half2_rn(acc[nt][0], acc[nt][1]);
            *(__half2*)&op[q1 + nt * 8 + 2 * c4] = __floats2half2_rn(acc[nt][2], acc[nt][3]);
        }
    }
}

// ---------------- kernel 5: fp16 mma flash attention (cp.async double buffer) ----------------
__global__ void __launch_bounds__(256, 2) k_attn(const float* __restrict__ mask) {
    extern __shared__ __half smh[];
    // layout: K0 | V0 | K1 | V1, each 64*HP halves
    int tid = threadIdx.x;
    int w = tid >> 5, lane = tid & 31;
    int r4 = lane >> 2, c4 = lane & 3;
    int qt = blockIdx.x & 7;
    int bh = blockIdx.x >> 3;
    int h = bh & 7, b = bh >> 3;
    size_t base = (size_t)bh * S * HD;
    int qw = qt * 128 + w * 16;

    unsigned s_u = (unsigned)__cvta_generic_to_shared(smh);
    unsigned sK_u[2] = {s_u, s_u + 2u * 64 * HP * 2};
    unsigned sV_u[2] = {s_u + 64u * HP * 2, s_u + 3u * 64 * HP * 2};

    unsigned krow = ((lane & 7) * HP + ((lane >> 3) << 3)) * 2;
    unsigned vrow = ((((lane >> 3) & 1) * 8 + (lane & 7)) * HP + ((lane >> 4) << 3)) * 2;

    // staging coordinates: 2 chunks of 16B each for K and V per thread
    int srow0 = tid >> 3, sc0 = (tid & 7) * 8;
    int srow1 = (tid + 256) >> 3, sc1 = ((tid + 256) & 7) * 8;
    const __half* gk0 = g_k + base;
    const __half* gv0 = g_v + base;

    // prologue: stage tile 0
    cpa16(sK_u[0] + (srow0 * HP + sc0) * 2, gk0 + srow0 * 64 + sc0);
    cpa16(sK_u[0] + (srow1 * HP + sc1) * 2, gk0 + srow1 * 64 + sc1);
    cpa16(sV_u[0] + (srow0 * HP + sc0) * 2, gv0 + srow0 * 64 + sc0);
    cpa16(sV_u[0] + (srow1 * HP + sc1) * 2, gv0 + srow1 * 64 + sc1);
    CP_COMMIT();

    // Q fragments from global
    unsigned qa[4][4];
    {
        const __half* qb = g_q + base + (size_t)qw * HD;
        #pragma unroll
        for (int kk = 0; kk < 4; kk++) {
            qa[kk][0] = *(const unsigned*)&qb[r4 * 64 + kk * 16 + 2 * c4];
            qa[kk][1] = *(const unsigned*)&qb[(r4 + 8) * 64 + kk * 16 + 2 * c4];
            qa[kk][2] = *(const unsigned*)&qb[r4 * 64 + kk * 16 + 2 * c4 + 8];
            qa[kk][3] = *(const unsigned*)&qb[(r4 + 8) * 64 + kk * 16 + 2 * c4 + 8];
        }
    }

    float o[8][4];
    #pragma unroll
    for (int nt = 0; nt < 8; nt++)
        #pragma unroll
        for (int j = 0; j < 4; j++) o[nt][j] = 0.f;
    float m0 = -1e30f, m1 = -1e30f, l0 = 0.f, l1 = 0.f;

    const float* mrow0 = mask + ((size_t)h * S + qw + r4) * S;
    const float* mrow1 = mrow0 + (size_t)8 * S;

    for (int kt = 0; kt < S / 64; kt++) {
        int cur = kt & 1;
        CP_WAIT0();
        __syncthreads();
        if (kt < S / 64 - 1) {
            int nxt = cur ^ 1;
            const __half* gk = gk0 + (size_t)(kt + 1) * 64 * 64;
            const __half* gv = gv0 + (size_t)(kt + 1) * 64 * 64;
            cpa16(sK_u[nxt] + (srow0 * HP + sc0) * 2, gk + srow0 * 64 + sc0);
            cpa16(sK_u[nxt] + (srow1 * HP + sc1) * 2, gk + srow1 * 64 + sc1);
            cpa16(sV_u[nxt] + (srow0 * HP + sc0) * 2, gv + srow0 * 64 + sc0);
            cpa16(sV_u[nxt] + (srow1 * HP + sc1) * 2, gv + srow1 * 64 + sc1);
            CP_COMMIT();
        }

        // energy = Q K^T
        float e[8][4];
        #pragma unroll
        for (int nt = 0; nt < 8; nt++) {
            #pragma unroll
            for (int j = 0; j < 4; j++) e[nt][j] = 0.f;
            unsigned kb0 = sK_u[cur] + nt * 8 * HP * 2 + krow;
            unsigned bf[4], bf2[4];
            ldmx4(bf, kb0);
            ldmx4(bf2, kb0 + 64);
            mma_f16(e[nt], qa[0], bf[0], bf[1]);
            mma_f16(e[nt], qa[1], bf[2], bf[3]);
            mma_f16(e[nt], qa[2], bf2[0], bf2[1]);
            mma_f16(e[nt], qa[3], bf2[2], bf2[3]);
        }

        // mask * scale
        int kb = kt * 64;
        #pragma unroll
        for (int nt = 0; nt < 8; nt++) {
            float2 mm0 = *(const float2*)&mrow0[kb + nt * 8 + 2 * c4];
            float2 mm1 = *(const float2*)&mrow1[kb + nt * 8 + 2 * c4];
            e[nt][0] *= mm0.x * SCALE;
            e[nt][1] *= mm0.y * SCALE;
            e[nt][2] *= mm1.x * SCALE;
            e[nt][3] *= mm1.y * SCALE;
        }

        // online softmax
        float rm0 = -1e30f, rm1 = -1e30f;
        #pragma unroll
        for (int nt = 0; nt < 8; nt++) {
            rm0 = fmaxf(rm0, fmaxf(e[nt][0], e[nt][1]));
            rm1 = fmaxf(rm1, fmaxf(e[nt][2], e[nt][3]));
        }
        rm0 = fmaxf(rm0, __shfl_xor_sync(0xffffffffu, rm0, 1));
        rm0 = fmaxf(rm0, __shfl_xor_sync(0xffffffffu, rm0, 2));
        rm1 = fmaxf(rm1, __shfl_xor_sync(0xffffffffu, rm1, 1));
        rm1 = fmaxf(rm1, __shfl_xor_sync(0xffffffffu, rm1, 2));
        float mn0 = fmaxf(m0, rm0), mn1 = fmaxf(m1, rm1);
        float a0 = __expf(m0 - mn0), a1 = __expf(m1 - mn1);
        float rs0 = 0.f, rs1 = 0.f;
        #pragma unroll
        for (int nt = 0; nt < 8; nt++) {
            e[nt][0] = __expf(e[nt][0] - mn0);
            e[nt][1] = __expf(e[nt][1] - mn0);
            e[nt][2] = __expf(e[nt][2] - mn1);
            e[nt][3] = __expf(e[nt][3] - mn1);
            rs0 += e[nt][0] + e[nt][1];
            rs1 += e[nt][2] + e[nt][3];
        }
        rs0 += __shfl_xor_sync(0xffffffffu, rs0, 1);
        rs0 += __shfl_xor_sync(0xffffffffu, rs0, 2);
        rs1 += __shfl_xor_sync(0xffffffffu, rs1, 1);
        rs1 += __shfl_xor_sync(0xffffffffu, rs1, 2);
        l0 = l0 * a0 + rs0;
        l1 = l1 * a1 + rs1;
        m0 = mn0; m1 = mn1;

        #pragma unroll
        for (int nt = 0; nt < 8; nt++) {
            o[nt][0] *= a0; o[nt][1] *= a0;
            o[nt][2] *= a1; o[nt][3] *= a1;
        }

        // O += P V : P accumulator -> A fragments directly; V via ldmatrix.trans
        #pragma unroll
        for (int kk = 0; kk < 4; kk++) {
            unsigned pa[4];
            pa[0] = h2u(e[2 * kk][0], e[2 * kk][1]);
            pa[1] = h2u(e[2 * kk][2], e[2 * kk][3]);
            pa[2] = h2u(e[2 * kk + 1][0], e[2 * kk + 1][1]);
            pa[3] = h2u(e[2 * kk + 1][2], e[2 * kk + 1][3]);
            #pragma unroll
            for (int ntp = 0; ntp < 4; ntp++) {
                unsigned vf[4];
                ldmx4t(vf, sV_u[cur] + (kk * 16 * HP + ntp * 16) * 2 + vrow);
                mma_f16(o[2 * ntp], pa, vf[0], vf[1]);
                mma_f16(o[2 * ntp + 1], pa, vf[2], vf[3]);
            }
        }
    }

    float inv0 = 1.f / l0, inv1 = 1.f / l1;
    size_t ob0 = ((size_t)(b * S + qw + r4)) * D + h * 64;
    size_t ob1 = ((size_t)(b * S + qw + r4 + 8)) * D + h * 64;
    #pragma unroll
    for (int nt = 0; nt < 8; nt++) {
        *(__half2*)&g_att[ob0 + nt * 8 + 2 * c4] = __floats2half2_rn(o[nt][0] * inv0, o[nt][1] * inv0);
        *(__half2*)&g_att[ob1 + nt * 8 + 2 * c4] = __floats2half2_rn(o[nt][2] * inv1, o[nt][3] * inv1);
    }
}

// ---------------- kernel 6: out = att @ Wo^T + bo (double-buffered fp16 mma) ----------------
__global__ void __launch_bounds__(256, 2) k_proj(const float* __restrict__ Wo,
                                                 const float* __restrict__ bo,
                                                 float* __restrict__ out) {
    extern __shared__ __half smh[];
    // layout: A0 | A1 | B0 | B1  (A: 128*HP, B: 64*HP)
    __half* sA[2] = {smh, smh + 128 * HP};
    __half* sB[2] = {smh + 2 * 128 * HP, smh + 2 * 128 * HP + 64 * HP};
    int tid = threadIdx.x;
    int w = tid >> 5, lane = tid & 31;
    int r4 = lane >> 2, c4 = lane & 3;
    int m0 = blockIdx.x * 128;
    int n0 = blockIdx.y * 64;

    unsigned s_u = (unsigned)__cvta_generic_to_shared(smh);
    unsigned sA_u[2] = {s_u, s_u + 128u * HP * 2};

    float acc[8][4];
    #pragma unroll
    for (int nt = 0; nt < 8; nt++)
        #pragma unroll
        for (int j = 0; j < 4; j++) acc[nt][j] = 0.f;

    // staging helpers (A: 1024 chunks of 8 halves; each thread 4)
    auto stageA = [&](int buf, int k0) {
        #pragma unroll
        for (int t = 0; t < 4; t++) {
            int idx = tid + t * 256;
            int r = idx >> 3, c = (idx & 7) * 8;
            cpa16(sA_u[buf] + (r * HP + c) * 2, &g_att[(size_t)(m0 + r) * D + k0 + c]);
        }
    };
    auto stageB = [&](int buf, int k0) {
        #pragma unroll
        for (int t = 0; t < 4; t++) {
            int idx = tid + t * 256;
            int r = idx >> 4, c = (idx & 15) * 4;
            float4 v = *(const float4*)&Wo[(size_t)(n0 + r) * D + k0 + c];
            *(__half2*)&sB[buf][r * HP + c] = __floats2half2_rn(v.x, v.y);
            *(__half2*)&sB[buf][r * HP + c + 2] = __floats2half2_rn(v.z, v.w);
        }
    };

    stageA(0, 0);
    CP_COMMIT();
    stageB(0, 0);

    for (int kt = 0; kt < D / 64; kt++) {
        int cur = kt & 1;
        CP_WAIT0();
        __syncthreads();
        if (kt < D / 64 - 1) {
            stageA(cur ^ 1, (kt + 1) * 64);
            CP_COMMIT();
            stageB(cur ^ 1, (kt + 1) * 64);
        }

        const __half* Aw = sA[cur] + (w * 16) * HP;
        unsigned af[4][4];
        #pragma unroll
        for (int kk = 0; kk < 4; kk++) {
            af[kk][0] = *(const unsigned*)&Aw[r4 * HP + kk * 16 + 2 * c4];
            af[kk][1] = *(const unsigned*)&Aw[(r4 + 8) * HP + kk * 16 + 2 * c4];
            af[kk][2] = *(const unsigned*)&Aw[r4 * HP + kk * 16 + 2 * c4 + 8];
            af[kk][3] = *(const unsigned*)&Aw[(r4 + 8) * HP + kk * 16 + 2 * c4 + 8];
        }
        #pragma unroll
        for (int nt = 0; nt < 8; nt++) {
            #pragma unroll
            for (int kk = 0; kk < 4; kk++) {
                const __half* bp = &sB[cur][(nt * 8 + r4) * HP + kk * 16 + 2 * c4];
                unsigned b0 = *(const unsigned*)bp;
                unsigned b1 = *(const unsigned*)(bp + 8);
                mma_f16(acc[nt], af[kk], b0, b1);
            }
        }
    }

    int row0 = m0 + w * 16 + r4;
    #pragma unroll
    for (int nt = 0; nt < 8; nt++) {
        int n = n0 + nt * 8 + 2 * c4;
        float2 bb = *(const float2*)&bo[n];
        float2 v0, v1;
        v0.x = acc[nt][0] + bb.x; v0.y = acc[nt][1] + bb.y;
        v1.x = acc[nt][2] + bb.x; v1.y = acc[nt][3] + bb.y;
        *(float2*)&out[(size_t)row0 * D + n] = v0;
        *(float2*)&out[(size_t)(row0 + 8) * D + n] = v1;
    }
}

// ---------------- launch ----------------
extern "C" void kernel_launch(void* const* d_in, const int* in_sizes, int n_in,
                              void* d_out, int out_size) {
    const int*   x   = (const int*)d_in[0];
    const float* emb = (const float*)d_in[1];
    const float* Wq  = (const float*)d_in[2];
    const float* Wk  = (const float*)d_in[3];
    const float* Wv  = (const float*)d_in[4];
    const float* Wo  = (const float*)d_in[5];
    const float* bo  = (const float*)d_in[6];
    const float* Wc  = (const float*)d_in[7];
    const float* bc  = (const float*)d_in[8];
    float* out = (float*)d_out;
    float* maskout = out + (size_t)B * S * D;

    k_pe<<<S, 256>>>();
    k_embed<<<BS, 128>>>(x, emb, Wc, bc);
    k_norm<<<B, S>>>();
    dim3 mg(S, B);
    k_mask<<<mg, 256>>>(maskout);

    size_t qkv_smem = (128 * HP + 3 * 64 * HP) * sizeof(__half);
    cudaFuncSetAttribute(k_qkv, cudaFuncAttributeMaxDynamicSharedMemorySize, (int)qkv_smem);
    dim3 qg(BS / 128, H);
    k_qkv<<<qg, 256, qkv_smem>>>(Wq, Wk, Wv);

    size_t attn_smem = 4 * 64 * HP * sizeof(__half);           // 36864 B
    cudaFuncSetAttribute(k_attn, cudaFuncAttributeMaxDynamicSharedMemorySize, (int)attn_smem);
    k_attn<<<B * H * (S / 128), 256, attn_smem>>>(maskout);

    size_t proj_smem = (2 * 128 * HP + 2 * 64 * HP) * sizeof(__half);  // 55296 B
    cudaFuncSetAttribute(k_proj, cudaFuncAttributeMaxDynamicSharedMemorySize, (int)proj_smem);
    dim3 pg(BS / 128, D / 64);
    k_proj<<<pg, 256, proj_smem>>>(Wo, bo, out);
}

// round 9
// speedup vs baseline: 10.0635x; 1.0653x over previous
#include <cuda_runtime.h>
#include <cuda_fp16.h>
#include <math.h>

#define B 8
#define S 1024
#define D 512
#define H 8
#define HD 64
#define BS (B*S)
#define SCALE 0.044194173824159216f   // 1/sqrt(512)
#define SC2   0.063762069120577f      // SCALE * log2(e)
#define HP 72   // half-element row pad: ldmatrix row banks 4r%32 conflict-free

// ---------------- scratch (static device globals; no allocation) ----------------
__device__ float  g_pe[S * D];
__device__ float  g_w[BS];
__device__ __half g_hh[BS * D];
__device__ __half g_q[B * H * S * HD];   // [b,h,s,d]
__device__ __half g_k[B * H * S * HD];
__device__ __half g_v[B * H * S * HD];
__device__ __half g_att[BS * D];

// ---------------- helpers ----------------
__device__ __forceinline__ void mma_f16(float d[4], const unsigned a[4],
                                        unsigned b0, unsigned b1) {
    asm("mma.sync.aligned.m16n8k16.row.col.f32.f16.f16.f32 "
        "{%0,%1,%2,%3}, {%4,%5,%6,%7}, {%8,%9}, {%0,%1,%2,%3};"
        : "+f"(d[0]), "+f"(d[1]), "+f"(d[2]), "+f"(d[3])
        : "r"(a[0]), "r"(a[1]), "r"(a[2]), "r"(a[3]), "r"(b0), "r"(b1));
}
__device__ __forceinline__ void ldmx4(unsigned r[4], unsigned addr) {
    asm volatile("ldmatrix.sync.aligned.m8n8.x4.shared.b16 {%0,%1,%2,%3}, [%4];"
        : "=r"(r[0]), "=r"(r[1]), "=r"(r[2]), "=r"(r[3]) : "r"(addr));
}
__device__ __forceinline__ void ldmx4t(unsigned r[4], unsigned addr) {
    asm volatile("ldmatrix.sync.aligned.m8n8.x4.trans.shared.b16 {%0,%1,%2,%3}, [%4];"
        : "=r"(r[0]), "=r"(r[1]), "=r"(r[2]), "=r"(r[3]) : "r"(addr));
}
__device__ __forceinline__ unsigned h2u(float a, float b) {
    __half2 h = __floats2half2_rn(a, b);
    return *(unsigned*)&h;
}
__device__ __forceinline__ void cpa16(unsigned dst, const void* src) {
    asm volatile("cp.async.cg.shared.global [%0], [%1], 16;" :: "r"(dst), "l"(src));
}
#define CP_COMMIT() asm volatile("cp.async.commit_group;")
#define CP_WAIT0()  asm volatile("cp.async.wait_group 0;")

// ---------------- kernel 0: PE table ----------------
__global__ void k_pe() {
    int s = blockIdx.x;
    const float c = -logf(10000.0f) / (float)D;
    #pragma unroll
    for (int t = 0; t < 2; t++) {
        int d = threadIdx.x + t * 256;
        int i2 = d & ~1;
        float ang = (float)s * expf(c * (float)i2);
        g_pe[s * D + d] = (d & 1) ? cosf(ang) : sinf(ang);
    }
}

// ---------------- kernel 1: h = emb[x]+PE, width dot ----------------
__global__ void __launch_bounds__(128) k_embed(const int* __restrict__ x,
                                               const float* __restrict__ emb,
                                               const float* __restrict__ Wc,
                                               const float* __restrict__ bc) {
    int bs = blockIdx.x;
    int s = bs & (S - 1);
    int tok = x[bs];
    int t = threadIdx.x;
    const float4* e4 = (const float4*)(emb + (size_t)tok * D);
    const float4* p4 = (const float4*)(g_pe + (size_t)s * D);
    const float4* w4 = (const float4*)Wc;

    float4 e = e4[t], p = p4[t], w = w4[t];
    float4 hv;
    hv.x = e.x + p.x; hv.y = e.y + p.y; hv.z = e.z + p.z; hv.w = e.w + p.w;
    __half2* hh = (__half2*)(g_hh + (size_t)bs * D + t * 4);
    hh[0] = __floats2half2_rn(hv.x, hv.y);
    hh[1] = __floats2half2_rn(hv.z, hv.w);
    float wsum = hv.x * w.x + hv.y * w.y + hv.z * w.z + hv.w * w.w;

    #pragma unroll
    for (int off = 16; off; off >>= 1)
        wsum += __shfl_xor_sync(0xffffffffu, wsum, off);
    __shared__ float red[4];
    if ((t & 31) == 0) red[t >> 5] = wsum;
    __syncthreads();
    if (t == 0)
        g_w[bs] = red[0] + red[1] + red[2] + red[3] + bc[0];
}

// ---------------- kernel 2: per-batch min-max normalize ----------------
__global__ void k_norm() {
    int b = blockIdx.x;
    int t = threadIdx.x;
    float v = g_w[b * S + t];
    float mn = v, mx = v;
    __shared__ float smin[32], smax[32];
    #pragma unroll
    for (int off = 16; off; off >>= 1) {
        mn = fminf(mn, __shfl_xor_sync(0xffffffffu, mn, off));
        mx = fmaxf(mx, __shfl_xor_sync(0xffffffffu, mx, off));
    }
    if ((t & 31) == 0) { smin[t >> 5] = mn; smax[t >> 5] = mx; }
    __syncthreads();
    if (t < 32) {
        mn = smin[t]; mx = smax[t];
        #pragma unroll
        for (int off = 16; off; off >>= 1) {
            mn = fminf(mn, __shfl_xor_sync(0xffffffffu, mn, off));
            mx = fmaxf(mx, __shfl_xor_sync(0xffffffffu, mx, off));
        }
        if (t == 0) { smin[0] = mn; smax[0] = mx; }
    }
    __syncthreads();
    float lo = smin[0], hi = smax[0];
    g_w[b * S + t] = (v - lo) / (hi - lo);
}

// ---------------- kernel 3: mask ----------------
__global__ void __launch_bounds__(256) k_mask(float* __restrict__ mout) {
    int i = blockIdx.x, b = blockIdx.y;
    float w = g_w[b * S + i];
    float4* mrow4 = (float4*)(mout + ((size_t)b * S + i) * S);
    bool lower = (i < S / 2);
    int j0 = threadIdx.x * 4;
    float r[4];
    #pragma unroll
    for (int u = 0; u < 4; u++) {
        int j = j0 + u;
        int idx = (S / 2 - 1 - i + j) & (S - 1);
        float origin = (idx < S / 2) ? (1.0f - (float)idx * (1.0f / (float)(S / 2 - 1)))
                                     : ((float)(idx - S / 2) * (1.0f / (float)(S / 2 - 1)));
        bool cmp = (idx >= j);
        bool move = lower ? cmp : !cmp;
        float val = 0.f;
        if (move) {
            float z = (origin - w) * 100.f;
            val = 1.f / (1.f + __expf(z));
        }
        r[u] = val;
    }
    mrow4[threadIdx.x] = make_float4(r[0], r[1], r[2], r[3]);
}

// ---------------- kernel 4: QKV via fp16 mma ----------------
__global__ void __launch_bounds__(256) k_qkv(const float* __restrict__ Wq,
                                             const float* __restrict__ Wk,
                                             const float* __restrict__ Wv) {
    extern __shared__ __half smh[];
    __half* sA = smh;                 // 128 x 72
    __half* sB = smh + 128 * HP;      // 3 x 64 x 72
    int tid = threadIdx.x;
    int w = tid >> 5, lane = tid & 31;
    int r4 = lane >> 2, c4 = lane & 3;
    int m0 = blockIdx.x * 128;
    int h = blockIdx.y;

    #pragma unroll
    for (int t = 0; t < 8; t++) {
        int idx = tid + t * 256;
        int r = idx >> 4, c = (idx & 15) * 4;
        uint2 q = *(const uint2*)&g_hh[(size_t)(m0 + r) * D + h * 64 + c];
        *(uint2*)&sA[r * HP + c] = q;
    }
    const float* Ws[3] = {Wq, Wk, Wv};
    #pragma unroll
    for (int wi = 0; wi < 3; wi++) {
        #pragma unroll
        for (int t = 0; t < 4; t++) {
            int idx = tid + t * 256;
            int r = idx >> 4, c = (idx & 15) * 4;
            float4 v = *(const float4*)&Ws[wi][(size_t)r * 64 + c];
            *(__half2*)&sB[(wi * 64 + r) * HP + c] = __floats2half2_rn(v.x, v.y);
            *(__half2*)&sB[(wi * 64 + r) * HP + c + 2] = __floats2half2_rn(v.z, v.w);
        }
    }
    __syncthreads();

    const __half* Aw = sA + (w * 16) * HP;
    unsigned af[4][4];
    #pragma unroll
    for (int kk = 0; kk < 4; kk++) {
        af[kk][0] = *(const unsigned*)&Aw[r4 * HP + kk * 16 + 2 * c4];
        af[kk][1] = *(const unsigned*)&Aw[(r4 + 8) * HP + kk * 16 + 2 * c4];
        af[kk][2] = *(const unsigned*)&Aw[r4 * HP + kk * 16 + 2 * c4 + 8];
        af[kk][3] = *(const unsigned*)&Aw[(r4 + 8) * HP + kk * 16 + 2 * c4 + 8];
    }

    int row0 = m0 + w * 16 + r4;
    __half* outs[3] = {g_q, g_k, g_v};
    #pragma unroll
    for (int wi = 0; wi < 3; wi++) {
        float acc[8][4];
        #pragma unroll
        for (int nt = 0; nt < 8; nt++) {
            #pragma unroll
            for (int j = 0; j < 4; j++) acc[nt][j] = 0.f;
            #pragma unroll
            for (int kk = 0; kk < 4; kk++) {
                const __half* bp = &sB[(wi * 64 + nt * 8 + r4) * HP + kk * 16 + 2 * c4];
                unsigned b0 = *(const unsigned*)bp;
                unsigned b1 = *(const unsigned*)(bp + 8);
                mma_f16(acc[nt], af[kk], b0, b1);
            }
        }
        int b0r = row0 >> 10, s0 = row0 & (S - 1);
        int b1r = (row0 + 8) >> 10, s1 = (row0 + 8) & (S - 1);
        size_t q0 = (((size_t)b0r * H + h) * S + s0) * HD;
        size_t q1 = (((size_t)b1r * H + h) * S + s1) * HD;
        __half* op = outs[wi];
        #pragma unroll
        for (int nt = 0; nt < 8; nt++) {
            *(__half2*)&op[q0 + nt * 8 + 2 * c4] = __floats2half2_rn(acc[nt][0], acc[nt][1]);
            *(__half2*)&op[q1 + nt * 8 + 2 * c4] = __floats2half2_rn(acc[nt][2], acc[nt][3]);
        }
    }
}

// ---------------- kernel 5: fp16 mma flash attention ----------------
// No-shift softmax: energies are bounded (|e| < ~3), softmax is shift-invariant,
// so p = exp(e) directly. No max-tracking, no per-tile shuffles, no O rescale;
// l reduced across the quad once at the end.
__global__ void __launch_bounds__(256, 2) k_attn(const float* __restrict__ mask) {
    extern __shared__ __half smh[];
    int tid = threadIdx.x;
    int w = tid >> 5, lane = tid & 31;
    int r4 = lane >> 2, c4 = lane & 3;
    int qt = blockIdx.x & 7;
    int bh = blockIdx.x >> 3;
    int h = bh & 7, b = bh >> 3;
    size_t base = (size_t)bh * S * HD;
    int qw = qt * 128 + w * 16;

    unsigned s_u = (unsigned)__cvta_generic_to_shared(smh);
    unsigned sK_u[2] = {s_u, s_u + 2u * 64 * HP * 2};
    unsigned sV_u[2] = {s_u + 64u * HP * 2, s_u + 3u * 64 * HP * 2};

    unsigned krow = ((lane & 7) * HP + ((lane >> 3) << 3)) * 2;
    unsigned vrow = ((((lane >> 3) & 1) * 8 + (lane & 7)) * HP + ((lane >> 4) << 3)) * 2;

    int srow0 = tid >> 3, sc0 = (tid & 7) * 8;
    int srow1 = (tid + 256) >> 3, sc1 = ((tid + 256) & 7) * 8;
    const __half* gk0 = g_k + base;
    const __half* gv0 = g_v + base;

    // prologue: stage tile 0
    cpa16(sK_u[0] + (srow0 * HP + sc0) * 2, gk0 + srow0 * 64 + sc0);
    cpa16(sK_u[0] + (srow1 * HP + sc1) * 2, gk0 + srow1 * 64 + sc1);
    cpa16(sV_u[0] + (srow0 * HP + sc0) * 2, gv0 + srow0 * 64 + sc0);
    cpa16(sV_u[0] + (srow1 * HP + sc1) * 2, gv0 + srow1 * 64 + sc1);
    CP_COMMIT();

    // Q fragments from global
    unsigned qa[4][4];
    {
        const __half* qb = g_q + base + (size_t)qw * HD;
        #pragma unroll
        for (int kk = 0; kk < 4; kk++) {
            qa[kk][0] = *(const unsigned*)&qb[r4 * 64 + kk * 16 + 2 * c4];
            qa[kk][1] = *(const unsigned*)&qb[(r4 + 8) * 64 + kk * 16 + 2 * c4];
            qa[kk][2] = *(const unsigned*)&qb[r4 * 64 + kk * 16 + 2 * c4 + 8];
            qa[kk][3] = *(const unsigned*)&qb[(r4 + 8) * 64 + kk * 16 + 2 * c4 + 8];
        }
    }

    float o[8][4];
    #pragma unroll
    for (int nt = 0; nt < 8; nt++)
        #pragma unroll
        for (int j = 0; j < 4; j++) o[nt][j] = 0.f;
    float l0 = 0.f, l1 = 0.f;

    const float* mrow0 = mask + ((size_t)h * S + qw + r4) * S;
    const float* mrow1 = mrow0 + (size_t)8 * S;

    for (int kt = 0; kt < S / 64; kt++) {
        int cur = kt & 1;
        CP_WAIT0();
        __syncthreads();
        if (kt < S / 64 - 1) {
            int nxt = cur ^ 1;
            const __half* gk = gk0 + (size_t)(kt + 1) * 64 * 64;
            const __half* gv = gv0 + (size_t)(kt + 1) * 64 * 64;
            cpa16(sK_u[nxt] + (srow0 * HP + sc0) * 2, gk + srow0 * 64 + sc0);
            cpa16(sK_u[nxt] + (srow1 * HP + sc1) * 2, gk + srow1 * 64 + sc1);
            cpa16(sV_u[nxt] + (srow0 * HP + sc0) * 2, gv + srow0 * 64 + sc0);
            cpa16(sV_u[nxt] + (srow1 * HP + sc1) * 2, gv + srow1 * 64 + sc1);
            CP_COMMIT();
        }

        // energy = Q K^T
        float e[8][4];
        #pragma unroll
        for (int nt = 0; nt < 8; nt++) {
            #pragma unroll
            for (int j = 0; j < 4; j++) e[nt][j] = 0.f;
            unsigned kb0 = sK_u[cur] + nt * 8 * HP * 2 + krow;
            unsigned bf[4], bf2[4];
            ldmx4(bf, kb0);
            ldmx4(bf2, kb0 + 64);
            mma_f16(e[nt], qa[0], bf[0], bf[1]);
            mma_f16(e[nt], qa[1], bf[2], bf[3]);
            mma_f16(e[nt], qa[2], bf2[0], bf2[1]);
            mma_f16(e[nt], qa[3], bf2[2], bf2[3]);
        }

        // p = exp2(qk * mask * SC2); accumulate l
        int kb = kt * 64;
        #pragma unroll
        for (int nt = 0; nt < 8; nt++) {
            float2 mm0 = *(const float2*)&mrow0[kb + nt * 8 + 2 * c4];
            float2 mm1 = *(const float2*)&mrow1[kb + nt * 8 + 2 * c4];
            e[nt][0] = exp2f(e[nt][0] * (mm0.x * SC2));
            e[nt][1] = exp2f(e[nt][1] * (mm0.y * SC2));
            e[nt][2] = exp2f(e[nt][2] * (mm1.x * SC2));
            e[nt][3] = exp2f(e[nt][3] * (mm1.y * SC2));
            l0 += e[nt][0] + e[nt][1];
            l1 += e[nt][2] + e[nt][3];
        }

        // O += P V : P accumulator -> A fragments directly; V via ldmatrix.trans
        #pragma unroll
        for (int kk = 0; kk < 4; kk++) {
            unsigned pa[4];
            pa[0] = h2u(e[2 * kk][0], e[2 * kk][1]);
            pa[1] = h2u(e[2 * kk][2], e[2 * kk][3]);
            pa[2] = h2u(e[2 * kk + 1][0], e[2 * kk + 1][1]);
            pa[3] = h2u(e[2 * kk + 1][2], e[2 * kk + 1][3]);
            #pragma unroll
            for (int ntp = 0; ntp < 4; ntp++) {
                unsigned vf[4];
                ldmx4t(vf, sV_u[cur] + (kk * 16 * HP + ntp * 16) * 2 + vrow);
                mma_f16(o[2 * ntp], pa, vf[0], vf[1]);
                mma_f16(o[2 * ntp + 1], pa, vf[2], vf[3]);
            }
        }
    }

    // single end-of-loop reduction of l across the quad
    l0 += __shfl_xor_sync(0xffffffffu, l0, 1);
    l0 += __shfl_xor_sync(0xffffffffu, l0, 2);
    l1 += __shfl_xor_sync(0xffffffffu, l1, 1);
    l1 += __shfl_xor_sync(0xffffffffu, l1, 2);
    float inv0 = 1.f / l0, inv1 = 1.f / l1;
    size_t ob0 = ((size_t)(b * S + qw + r4)) * D + h * 64;
    size_t ob1 = ((size_t)(b * S + qw + r4 + 8)) * D + h * 64;
    #pragma unroll
    for (int nt = 0; nt < 8; nt++) {
        *(__half2*)&g_att[ob0 + nt * 8 + 2 * c4] = __floats2half2_rn(o[nt][0] * inv0, o[nt][1] * inv0);
        *(__half2*)&g_att[ob1 + nt * 8 + 2 * c4] = __floats2half2_rn(o[nt][2] * inv1, o[nt][3] * inv1);
    }
}

// ---------------- kernel 6: out = att @ Wo^T + bo (double-buffered fp16 mma) ----------------
__global__ void __launch_bounds__(256, 2) k_proj(const float* __restrict__ Wo,
                                                 const float* __restrict__ bo,
                                                 float* __restrict__ out) {
    extern __shared__ __half smh[];
    __half* sA[2] = {smh, smh + 128 * HP};
    __half* sB[2] = {smh + 2 * 128 * HP, smh + 2 * 128 * HP + 64 * HP};
    int tid = threadIdx.x;
    int w = tid >> 5, lane = tid & 31;
    int r4 = lane >> 2, c4 = lane & 3;
    int m0 = blockIdx.x * 128;
    int n0 = blockIdx.y * 64;

    unsigned s_u = (unsigned)__cvta_generic_to_shared(smh);
    unsigned sA_u[2] = {s_u, s_u + 128u * HP * 2};

    float acc[8][4];
    #pragma unroll
    for (int nt = 0; nt < 8; nt++)
        #pragma unroll
        for (int j = 0; j < 4; j++) acc[nt][j] = 0.f;

    auto stageA = [&](int buf, int k0) {
        #pragma unroll
        for (int t = 0; t < 4; t++) {
            int idx = tid + t * 256;
            int r = idx >> 3, c = (idx & 7) * 8;
            cpa16(sA_u[buf] + (r * HP + c) * 2, &g_att[(size_t)(m0 + r) * D + k0 + c]);
        }
    };
    auto stageB = [&](int buf, int k0) {
        #pragma unroll
        for (int t = 0; t < 4; t++) {
            int idx = tid + t * 256;
            int r = idx >> 4, c = (idx & 15) * 4;
            float4 v = *(const float4*)&Wo[(size_t)(n0 + r) * D + k0 + c];
            *(__half2*)&sB[buf][r * HP + c] = __floats2half2_rn(v.x, v.y);
            *(__half2*)&sB[buf][r * HP + c + 2] = __floats2half2_rn(v.z, v.w);
        }
    };

    stageA(0, 0);
    CP_COMMIT();
    stageB(0, 0);

    for (int kt = 0; kt < D / 64; kt++) {
        int cur = kt & 1;
        CP_WAIT0();
        __syncthreads();
        if (kt < D / 64 - 1) {
            stageA(cur ^ 1, (kt + 1) * 64);
            CP_COMMIT();
            stageB(cur ^ 1, (kt + 1) * 64);
        }

        const __half* Aw = sA[cur] + (w * 16) * HP;
        unsigned af[4][4];
        #pragma unroll
        for (int kk = 0; kk < 4; kk++) {
            af[kk][0] = *(const unsigned*)&Aw[r4 * HP + kk * 16 + 2 * c4];
            af[kk][1] = *(const unsigned*)&Aw[(r4 + 8) * HP + kk * 16 + 2 * c4];
            af[kk][2] = *(const unsigned*)&Aw[r4 * HP + kk * 16 + 2 * c4 + 8];
            af[kk][3] = *(const unsigned*)&Aw[(r4 + 8) * HP + kk * 16 + 2 * c4 + 8];
        }
        #pragma unroll
        for (int nt = 0; nt < 8; nt++) {
            #pragma unroll
            for (int kk = 0; kk < 4; kk++) {
                const __half* bp = &sB[cur][(nt * 8 + r4) * HP + kk * 16 + 2 * c4];
                unsigned b0 = *(const unsigned*)bp;
                unsigned b1 = *(const unsigned*)(bp + 8);
                mma_f16(acc[nt], af[kk], b0, b1);
            }
        }
    }

    int row0 = m0 + w * 16 + r4;
    #pragma unroll
    for (int nt = 0; nt < 8; nt++) {
        int n = n0 + nt * 8 + 2 * c4;
        float2 bb = *(const float2*)&bo[n];
        float2 v0, v1;
        v0.x = acc[nt][0] + bb.x; v0.y = acc[nt][1] + bb.y;
        v1.x = acc[nt][2] + bb.x; v1.y = acc[nt][3] + bb.y;
        *(float2*)&out[(size_t)row0 * D + n] = v0;
        *(float2*)&out[(size_t)(row0 + 8) * D + n] = v1;
    }
}

// ---------------- launch ----------------
extern "C" void kernel_launch(void* const* d_in, const int* in_sizes, int n_in,
                              void* d_out, int out_size) {
    const int*   x   = (const int*)d_in[0];
    const float* emb = (const float*)d_in[1];
    const float* Wq  = (const float*)d_in[2];
    const float* Wk  = (const float*)d_in[3];
    const float* Wv  = (const float*)d_in[4];
    const float* Wo  = (const float*)d_in[5];
    const float* bo  = (const float*)d_in[6];
    const float* Wc  = (const float*)d_in[7];
    const float* bc  = (const float*)d_in[8];
    float* out = (float*)d_out;
    float* maskout = out + (size_t)B * S * D;

    k_pe<<<S, 256>>>();
    k_embed<<<BS, 128>>>(x, emb, Wc, bc);
    k_norm<<<B, S>>>();
    dim3 mg(S, B);
    k_mask<<<mg, 256>>>(maskout);

    size_t qkv_smem = (128 * HP + 3 * 64 * HP) * sizeof(__half);
    cudaFuncSetAttribute(k_qkv, cudaFuncAttributeMaxDynamicSharedMemorySize, (int)qkv_smem);
    dim3 qg(BS / 128, H);
    k_qkv<<<qg, 256, qkv_smem>>>(Wq, Wk, Wv);

    size_t attn_smem = 4 * 64 * HP * sizeof(__half);
    cudaFuncSetAttribute(k_attn, cudaFuncAttributeMaxDynamicSharedMemorySize, (int)attn_smem);
    k_attn<<<B * H * (S / 128), 256, attn_smem>>>(maskout);

    size_t proj_smem = (2 * 128 * HP + 2 * 64 * HP) * sizeof(__half);
    cudaFuncSetAttribute(k_proj, cudaFuncAttributeMaxDynamicSharedMemorySize, (int)proj_smem);
    dim3 pg(BS / 128, D / 64);
    k_proj<<<pg, 256, proj_smem>>>(Wo, bo, out);
}